// round 9
// baseline (speedup 1.0000x reference)
#include <cuda_runtime.h>
#include <cuda_fp16.h>
#include <cstdint>

// Problem constants
#define TOK   65536      // B*L
#define BATCH 64
#define SEQL  1024
#define HID   512
#define FF    1024
#define HALF_ 256
#define VOC   32000

typedef __half half_t;

__device__ __forceinline__ uint32_t smem_u32(const void* p) {
    uint32_t a;
    asm("{ .reg .u64 t; cvta.to.shared.u64 t, %1; cvt.u32.u64 %0, t; }" : "=r"(a) : "l"(p));
    return a;
}
#define SW128(o) ((o) ^ (((o) >> 3) & 0x70))

__device__ __forceinline__ void ldsm4(uint32_t* r, uint32_t a) {
    asm volatile("ldmatrix.sync.aligned.m8n8.x4.shared.b16 {%0,%1,%2,%3}, [%4];"
        : "=r"(r[0]), "=r"(r[1]), "=r"(r[2]), "=r"(r[3]) : "r"(a));
}
__device__ __forceinline__ void mma16816(float* c, const uint32_t* a, const uint32_t* b) {
    asm volatile("mma.sync.aligned.m16n8k16.row.col.f32.f16.f16.f32 "
        "{%0,%1,%2,%3}, {%4,%5,%6,%7}, {%8,%9}, {%0,%1,%2,%3};"
        : "+f"(c[0]), "+f"(c[1]), "+f"(c[2]), "+f"(c[3])
        : "r"(a[0]), "r"(a[1]), "r"(a[2]), "r"(a[3]), "r"(b[0]), "r"(b[1]));
}
__device__ __forceinline__ void cp16(uint32_t dst, const void* src, bool pred) {
    const int sz = pred ? 16 : 0;
    asm volatile("cp.async.cg.shared.global [%0], [%1], 16, %2;"
        :: "r"(dst), "l"(src), "r"(sz) : "memory");
}
#define CP_COMMIT() asm volatile("cp.async.commit_group;" ::: "memory")
template<int N>
__device__ __forceinline__ void cp_wait() {
    asm volatile("cp.async.wait_group %0;" :: "n"(N) : "memory");
}

__device__ __forceinline__ void split2h(float x, half_t& h, half_t& l) {
    h = __float2half_rn(x);
    l = __float2half_rn(x - __half2float(h));
}

// -------- scratch (device globals) --------
__device__ half_t g_ah[(size_t)TOK * HID],  g_al[(size_t)TOK * HID];
__device__ half_t g_h1h[(size_t)TOK * FF],  g_h1l[(size_t)TOK * FF];
__device__ half_t g_hh[(size_t)TOK * HID],  g_hl[(size_t)TOK * HID];
__device__ float  g_x[(size_t)TOK * HID];
__device__ float  g_k[(size_t)TOK * HID];
__device__ half_t g_w1h[(size_t)FF * HID];
__device__ half_t g_w2h[(size_t)HID * FF];
__device__ half_t g_wph[(size_t)HID * HID];
__device__ half_t g_owh[(size_t)VOC * HID];
__device__ float  g_bproj[HID];
__device__ float  g_c[BATCH * HID];
__device__ half_t g_ch[BATCH * HID], g_cl[BATCH * HID];

// ============================================================
// mma.sync fp16 2-pass GEMM, cp.async 4-stage pipeline.
// C[M,N] = A[M,K] @ B^T;  A [M,K] K-major hi/lo fp16, B [N,K] single fp16.
// C = Ah*B + Al*B.
// 128x128 CTA tile, BK=32, 128 threads (4 warps, 64x64 each).
// A smem rows: 128B = [hi 64B | lo 64B]; B smem: two 64B rows per 128B
// line: off(n,k) = (n>>1)*128 + (n&1)*64 + k*2; SW128 swizzle everywhere.
// Stage = 16KB A + 8KB B = 24KB; 4 stages; one __syncthreads per chunk.
// EPI: 0 = relu(acc+bias) -> split fp16; 1 = acc+bias+embed[seq[m]] -> f32;
//      2 = acc+bias -> f32.
// ============================================================
#define ASTAGE 16384
#define GSTAGE 24576
#define NSTAGE 4
#define GSMEM  (NSTAGE * GSTAGE)

template<int EPI>
__global__ void __launch_bounds__(128, 2) mma_gemm(
    int Mrows, int N, int K,
    const half_t* __restrict__ Ah, const half_t* __restrict__ Al,
    const half_t* __restrict__ Bh,
    const float* __restrict__ bias,
    float* __restrict__ Cf, half_t* __restrict__ Chi, half_t* __restrict__ Clo,
    const int* __restrict__ seq, const float* __restrict__ embed)
{
    extern __shared__ __align__(1024) char smem[];
    const uint32_t sbase = smem_u32(smem);
    const int tid = threadIdx.x;
    const int bm = blockIdx.y * 128;
    const int bn = blockIdx.x * 128;
    const int wid = tid >> 5, lane = tid & 31;
    const int wm = (wid >> 1) * 64;     // warp row offset (0 / 64)
    const int wn = (wid & 1) * 64;      // warp col offset (0 / 64)
    const bool mguard = (Mrows & 127) != 0;

    // loader mapping: one thread per row (128 rows)
    const int lrow = tid;
    const int am = bm + lrow;
    const bool av = !mguard || (am < Mrows);
    const size_t aoff = (size_t)(av ? am : 0) * K;
    const size_t boff = (size_t)(bn + lrow) * K;
    const uint32_t bline = (uint32_t)((lrow >> 1) * 128 + (lrow & 1) * 64);

    // A ldmatrix lane addressing (m16 x k16 per x4)
    const int a_mi = lane >> 3;
    const int a_row = (lane & 7) + (a_mi & 1) * 8;
    const int a_kb = (a_mi >> 1) * 16;
    // B ldmatrix lane addressing (2 n8 tiles x 2 k-halves per x4)
    const int b_g = lane >> 3;
    const int b_row = lane & 7;
    const int b_nt = b_g >> 1;
    const int b_kh = (b_g & 1) * 16;

    float c[32][4];
#pragma unroll
    for (int i = 0; i < 32; i++)
#pragma unroll
        for (int j = 0; j < 4; j++) c[i][j] = 0.f;

    const int NCH = K >> 5;

    auto load_stage = [&](int s, int k0) {
        const uint32_t sA = sbase + s * GSTAGE;
        const uint32_t sB = sA + ASTAGE;
#pragma unroll
        for (int w = 0; w < 4; w++) {
            const uint32_t soh = SW128((uint32_t)(lrow * 128 + w * 16));
            const uint32_t sol = SW128((uint32_t)(lrow * 128 + 64 + w * 16));
            const size_t ko = (size_t)(k0 + w * 8);
            cp16(sA + soh, Ah + aoff + ko, av);
            cp16(sA + sol, Al + aoff + ko, av);
            cp16(sB + SW128(bline + w * 16), Bh + boff + ko, true);
        }
    };

    load_stage(0, 0);
    CP_COMMIT();
    load_stage(1, 32);
    CP_COMMIT();
    load_stage(2, 64);
    CP_COMMIT();

    int stage = 0;
    for (int ch = 0; ch < NCH; ch++) {
        cp_wait<2>();
        __syncthreads();
        if (ch + 3 < NCH) {
            int ns = stage + 3; if (ns >= NSTAGE) ns -= NSTAGE;
            load_stage(ns, (ch + 3) * 32);
        }
        CP_COMMIT();   // always commit (possibly empty) to keep accounting
        const uint32_t sAu = sbase + stage * GSTAGE;
        const uint32_t sBu = sAu + ASTAGE;
#pragma unroll
        for (int k16 = 0; k16 < 2; k16++) {
            const int kb = k16 * 32;
            uint32_t bfrag[4][4];
#pragma unroll
            for (int p = 0; p < 4; p++) {
                const int n = wn + (p * 2 + b_nt) * 8 + b_row;
                const uint32_t rb = (uint32_t)((n >> 1) * 128 + (n & 1) * 64);
                ldsm4(bfrag[p], sBu + SW128(rb + kb + b_kh));
            }
            uint32_t a[4][4];
#pragma unroll
            for (int mt = 0; mt < 4; mt++)
                ldsm4(a[mt], sAu + SW128((uint32_t)((wm + mt * 16 + a_row) * 128) + kb + a_kb));
#pragma unroll
            for (int mt = 0; mt < 4; mt++)
#pragma unroll
                for (int nt = 0; nt < 8; nt++)
                    mma16816(c[mt * 8 + nt], a[mt], &bfrag[nt >> 1][(nt & 1) * 2]);
            // lo(A) pass
#pragma unroll
            for (int mt = 0; mt < 4; mt++)
                ldsm4(a[mt], sAu + SW128((uint32_t)((wm + mt * 16 + a_row) * 128) + 64 + kb + a_kb));
#pragma unroll
            for (int mt = 0; mt < 4; mt++)
#pragma unroll
                for (int nt = 0; nt < 8; nt++)
                    mma16816(c[mt * 8 + nt], a[mt], &bfrag[nt >> 1][(nt & 1) * 2]);
        }
        if (++stage >= NSTAGE) stage = 0;
    }

    // ---- epilogue ----
    const int mrow = lane >> 2;
    const int mcol = (lane & 3) * 2;
#pragma unroll
    for (int mt = 0; mt < 4; mt++) {
        const int r0 = bm + wm + mt * 16 + mrow;
        const int r1 = r0 + 8;
        const bool v0 = !mguard || (r0 < Mrows);
        const bool v1 = !mguard || (r1 < Mrows);
        const float* e0 = nullptr;
        const float* e1 = nullptr;
        if (EPI == 1) {
            if (v0) e0 = embed + (size_t)seq[r0] * HID;
            if (v1) e1 = embed + (size_t)seq[r1] * HID;
        }
#pragma unroll
        for (int nt = 0; nt < 8; nt++) {
            const int col = bn + wn + nt * 8 + mcol;
            float* cc = c[mt * 8 + nt];
            const float b0v = bias[col], b1v = bias[col + 1];
            float x0 = cc[0] + b0v, x1 = cc[1] + b1v;
            float x2 = cc[2] + b0v, x3 = cc[3] + b1v;
            if (EPI == 0) {
                x0 = fmaxf(x0, 0.f); x1 = fmaxf(x1, 0.f);
                x2 = fmaxf(x2, 0.f); x3 = fmaxf(x3, 0.f);
                half_t h0, l0, h1, l1;
                if (v0) {
                    split2h(x0, h0, l0); split2h(x1, h1, l1);
                    __half2 ph; ph.x = h0; ph.y = h1;
                    __half2 pl; pl.x = l0; pl.y = l1;
                    *(__half2*)(Chi + (size_t)r0 * N + col) = ph;
                    *(__half2*)(Clo + (size_t)r0 * N + col) = pl;
                }
                if (v1) {
                    split2h(x2, h0, l0); split2h(x3, h1, l1);
                    __half2 ph; ph.x = h0; ph.y = h1;
                    __half2 pl; pl.x = l0; pl.y = l1;
                    *(__half2*)(Chi + (size_t)r1 * N + col) = ph;
                    *(__half2*)(Clo + (size_t)r1 * N + col) = pl;
                }
            } else {
                if (EPI == 1) {
                    if (v0) { x0 += e0[col]; x1 += e0[col + 1]; }
                    if (v1) { x2 += e1[col]; x3 += e1[col + 1]; }
                }
                if (v0) *(float2*)(Cf + (size_t)r0 * N + col) = make_float2(x0, x1);
                if (v1) *(float2*)(Cf + (size_t)r1 * N + col) = make_float2(x2, x3);
            }
        }
    }
}

// ============================================================
// gather + split:  Ahi/Alo[m] = split(embed[seq[m]])  (fp16)
// ============================================================
__global__ void __launch_bounds__(256) gsplit_k(const int* __restrict__ seq,
                                                const float* __restrict__ embed,
                                                half_t* __restrict__ hi, half_t* __restrict__ lo)
{
    const size_t idx = (size_t)blockIdx.x * 256 + threadIdx.x;   // TOK*64
    const int t = (int)(idx >> 6), c = (int)(idx & 63) * 8;
    const float* p = embed + (size_t)seq[t] * HID + c;
    float4 a = *(const float4*)p;
    float4 b = *(const float4*)(p + 4);
    float vv[8] = {a.x, a.y, a.z, a.w, b.x, b.y, b.z, b.w};
    const size_t ob = (size_t)t * HID + c;
#pragma unroll
    for (int j = 0; j < 8; j += 2) {
        half_t h0, l0, h1, l1;
        split2h(vv[j], h0, l0);
        split2h(vv[j + 1], h1, l1);
        __half2 ph; ph.x = h0; ph.y = h1;
        __half2 pl; pl.x = l0; pl.y = l1;
        *(__half2*)(hi + ob + j) = ph;
        *(__half2*)(lo + ob + j) = pl;
    }
}

// ============================================================
// Tiled transpose + round: W[K,N] fp32 -> out[N,K] single fp16.
// ============================================================
__global__ void __launch_bounds__(256) tsplit1_k(const float* __restrict__ W, int K, int N,
                                                 half_t* __restrict__ ht)
{
    __shared__ float t[32][33];
    const int tx = threadIdx.x & 31, ty = threadIdx.x >> 5;
    const int n0 = blockIdx.x * 32, k0 = blockIdx.y * 32;
#pragma unroll
    for (int i = 0; i < 4; i++)
        t[ty + 8 * i][tx] = W[(size_t)(k0 + ty + 8 * i) * N + n0 + tx];
    __syncthreads();
#pragma unroll
    for (int i = 0; i < 4; i++) {
        const size_t o = (size_t)(n0 + ty + 8 * i) * K + k0 + tx;
        ht[o] = __float2half_rn(t[tx][ty + 8 * i]);
    }
}

// ============================================================
// LayerNorm (warp per row) + split output to fp16 hi/lo.
// ============================================================
__global__ void __launch_bounds__(256) ln_split_k(const float* __restrict__ x,
                                                  const float* __restrict__ g,
                                                  const float* __restrict__ b,
                                                  half_t* __restrict__ hh, half_t* __restrict__ hl)
{
    const int row = blockIdx.x * 8 + (threadIdx.x >> 5);
    const int ln = threadIdx.x & 31;
    const float* xr = x + (size_t)row * HID + ln * 16;
    float v[16];
    *(float4*)&v[0]  = ((const float4*)xr)[0];
    *(float4*)&v[4]  = ((const float4*)xr)[1];
    *(float4*)&v[8]  = ((const float4*)xr)[2];
    *(float4*)&v[12] = ((const float4*)xr)[3];
    float s = 0.f;
#pragma unroll
    for (int j = 0; j < 16; j++) s += v[j];
#pragma unroll
    for (int o = 16; o; o >>= 1) s += __shfl_xor_sync(0xffffffffu, s, o);
    const float mean = s * (1.f / 512.f);
    float q = 0.f;
#pragma unroll
    for (int j = 0; j < 16; j++) { float d = v[j] - mean; q += d * d; }
#pragma unroll
    for (int o = 16; o; o >>= 1) q += __shfl_xor_sync(0xffffffffu, q, o);
    const float r = rsqrtf(q * (1.f / 512.f) + 1e-5f);
    const size_t ob = (size_t)row * HID + ln * 16;
#pragma unroll
    for (int j = 0; j < 16; j += 2) {
        const int c0 = ln * 16 + j;
        float y0 = (v[j] - mean) * r * g[c0] + b[c0];
        float y1 = (v[j + 1] - mean) * r * g[c0 + 1] + b[c0 + 1];
        half_t h0, l0, h1, l1;
        split2h(y0, h0, l0);
        split2h(y1, h1, l1);
        __half2 ph; ph.x = h0; ph.y = h1;
        __half2 pl; pl.x = l0; pl.y = l1;
        *(__half2*)(hh + ob + j) = ph;
        *(__half2*)(hl + ob + j) = pl;
    }
}

// ============================================================
__global__ void bpack_k(const float* __restrict__ sb, const float* __restrict__ eb)
{
    const int i = blockIdx.x * 256 + threadIdx.x;
    if (i < HID) g_bproj[i] = (i < HALF_) ? sb[i] : eb[i - HALF_];
}

// ============================================================
// Backward vector scan, 2 steps per iteration, inline norms,
// depth-2 row prefetch, fp32 + split-fp16 outputs.
// One warp per (batch, half) chain; 8 floats per lane.
//   s_t     = k_t . u_{t+1};  ws = w_t s;  us = ws / (||k_t||^2 + eps)
//   s_{t-1} = k_{t-1}.u_{t+1} - us_t (k_{t-1}.k_t)
// ============================================================
__global__ void __launch_bounds__(32) scan_k(const float* __restrict__ kall,
                                             float* __restrict__ cbuf,
                                             half_t* __restrict__ chh,
                                             half_t* __restrict__ chl)
{
    const int chain = blockIdx.x;
    const int b = chain >> 1, wh = chain & 1;
    const int ln = threadIdx.x;
    const float* base = kall + (size_t)b * SEQL * HID + wh * HALF_ + ln * 8;

#define LOADROW(dst, t) do { \
    float4 _a = *(const float4*)(base + (size_t)(t) * HID); \
    float4 _b = *(const float4*)(base + (size_t)(t) * HID + 4); \
    dst[0]=_a.x; dst[1]=_a.y; dst[2]=_a.z; dst[3]=_a.w; \
    dst[4]=_b.x; dst[5]=_b.y; dst[6]=_b.z; dst[7]=_b.w; } while (0)

    float u[8], acc[8], k0[8], k1[8], p0[8], p1[8];
    LOADROW(u, SEQL - 1);
#pragma unroll
    for (int j = 0; j < 8; j++) acc[j] = 0.f;

    // ---- single first step t = 1022 ----
    {
        float kc[8];
        LOADROW(kc, SEQL - 2);
        // issue next rows early
        LOADROW(k0, SEQL - 3);   // t=1021
        LOADROW(k1, SEQL - 4);   // t=1020
        LOADROW(p0, SEQL - 5);   // t=1019
        LOADROW(p1, SEQL - 6);   // t=1018
        float pa = 0.f, n0 = 0.f;
#pragma unroll
        for (int j = 0; j < 8; j++) { pa += kc[j] * u[j]; n0 += kc[j] * kc[j]; }
#pragma unroll
        for (int o = 16; o; o >>= 1) {
            pa += __shfl_xor_sync(0xffffffffu, pa, o);
            n0 += __shfl_xor_sync(0xffffffffu, n0, o);
        }
        const float w = wh ? (1023.f / 1024.f) : 1.f;
        const float ws = w * pa;
        const float us = ws / (n0 + 1e-6f);
#pragma unroll
        for (int j = 0; j < 8; j++) { acc[j] += ws * kc[j]; u[j] -= us * kc[j]; }
    }

    // ---- pair loop: t = 1021, 1019, ..., 1 (511 iterations) ----
    for (int t = SEQL - 3; t >= 1; t -= 2) {
        float q0[8] = {0, 0, 0, 0, 0, 0, 0, 0};
        float q1[8] = {0, 0, 0, 0, 0, 0, 0, 0};
        if (t >= 5) {
            LOADROW(q0, t - 4);
            LOADROW(q1, t - 5);
        }
        float pa = 0.f, pb = 0.f, pg = 0.f, n0 = 0.f, n1 = 0.f;
#pragma unroll
        for (int j = 0; j < 8; j++) {
            pa += k0[j] * u[j];
            pb += k1[j] * u[j];
            pg += k1[j] * k0[j];
            n0 += k0[j] * k0[j];
            n1 += k1[j] * k1[j];
        }
#pragma unroll
        for (int o = 16; o; o >>= 1) {
            pa += __shfl_xor_sync(0xffffffffu, pa, o);
            pb += __shfl_xor_sync(0xffffffffu, pb, o);
            pg += __shfl_xor_sync(0xffffffffu, pg, o);
            n0 += __shfl_xor_sync(0xffffffffu, n0, o);
            n1 += __shfl_xor_sync(0xffffffffu, n1, o);
        }
        const float inv1024 = 1.f / 1024.f;
        const float w0 = wh ? (float)(t + 1) * inv1024 : 1.f;
        const float w1 = wh ? (float)t * inv1024 : 1.f;
        const float id0 = 1.f / (n0 + 1e-6f);
        const float id1 = 1.f / (n1 + 1e-6f);
        const float ws0 = w0 * pa;
        const float us0 = ws0 * id0;
        const float s1 = pb - us0 * pg;
        const float ws1 = w1 * s1;
        const float us1 = ws1 * id1;
#pragma unroll
        for (int j = 0; j < 8; j++) {
            acc[j] += ws0 * k0[j] + ws1 * k1[j];
            u[j]   -= us0 * k0[j] + us1 * k1[j];
        }
        // rotate prefetch registers
#pragma unroll
        for (int j = 0; j < 8; j++) {
            k0[j] = p0[j]; k1[j] = p1[j];
            p0[j] = q0[j]; p1[j] = q1[j];
        }
    }

    const size_t ob = (size_t)b * HID + wh * HALF_ + ln * 8;
    *(float4*)(cbuf + ob)     = make_float4(acc[0], acc[1], acc[2], acc[3]);
    *(float4*)(cbuf + ob + 4) = make_float4(acc[4], acc[5], acc[6], acc[7]);
#pragma unroll
    for (int j = 0; j < 8; j += 2) {
        half_t h0, l0, h1, l1;
        split2h(acc[j], h0, l0);
        split2h(acc[j + 1], h1, l1);
        __half2 ph; ph.x = h0; ph.y = h1;
        __half2 pl; pl.x = l0; pl.y = l1;
        *(__half2*)(chh + ob + j) = ph;
        *(__half2*)(chl + ob + j) = pl;
    }
#undef LOADROW
}

// ============================================================
extern "C" void kernel_launch(void* const* d_in, const int* in_sizes, int n_in,
                              void* d_out, int out_size)
{
    const int*   seq   = (const int*)d_in[0];
    const float* embed = (const float*)d_in[1];
    const float* w1    = (const float*)d_in[2];
    const float* b1    = (const float*)d_in[3];
    const float* w2    = (const float*)d_in[4];
    const float* b2    = (const float*)d_in[5];
    const float* lng   = (const float*)d_in[6];
    const float* lnb   = (const float*)d_in[7];
    const float* sw    = (const float*)d_in[8];
    const float* sb    = (const float*)d_in[9];
    const float* ew    = (const float*)d_in[10];
    const float* eb    = (const float*)d_in[11];
    const float* ow    = (const float*)d_in[12];
    const float* ob    = (const float*)d_in[13];
    float* out = (float*)d_out;

    static bool init = false;
    static half_t *ah, *al, *h1h, *h1l, *hh, *hl, *w1h, *w2h, *wph, *owh, *ch, *cl;
    static float *xb, *kb, *bp, *cb;
    if (!init) {
        cudaGetSymbolAddress((void**)&ah,  g_ah);   cudaGetSymbolAddress((void**)&al,  g_al);
        cudaGetSymbolAddress((void**)&h1h, g_h1h);  cudaGetSymbolAddress((void**)&h1l, g_h1l);
        cudaGetSymbolAddress((void**)&hh,  g_hh);   cudaGetSymbolAddress((void**)&hl,  g_hl);
        cudaGetSymbolAddress((void**)&w1h, g_w1h);
        cudaGetSymbolAddress((void**)&w2h, g_w2h);
        cudaGetSymbolAddress((void**)&wph, g_wph);
        cudaGetSymbolAddress((void**)&owh, g_owh);
        cudaGetSymbolAddress((void**)&ch,  g_ch);   cudaGetSymbolAddress((void**)&cl,  g_cl);
        cudaGetSymbolAddress((void**)&xb,  g_x);
        cudaGetSymbolAddress((void**)&kb,  g_k);
        cudaGetSymbolAddress((void**)&bp,  g_bproj);
        cudaGetSymbolAddress((void**)&cb,  g_c);
        cudaFuncSetAttribute(mma_gemm<0>, cudaFuncAttributeMaxDynamicSharedMemorySize, GSMEM);
        cudaFuncSetAttribute(mma_gemm<1>, cudaFuncAttributeMaxDynamicSharedMemorySize, GSMEM);
        cudaFuncSetAttribute(mma_gemm<2>, cudaFuncAttributeMaxDynamicSharedMemorySize, GSMEM);
        init = true;
    }

    // weight transpose + fp16 round (B operands are [N,K] K-major, single fp16)
    tsplit1_k<<<dim3(FF / 32, HID / 32), 256>>>(w1, HID, FF, w1h);
    tsplit1_k<<<dim3(HID / 32, FF / 32), 256>>>(w2, FF, HID, w2h);
    tsplit1_k<<<dim3(HALF_ / 32, HID / 32), 256>>>(sw, HID, HALF_, wph);
    tsplit1_k<<<dim3(HALF_ / 32, HID / 32), 256>>>(ew, HID, HALF_, wph + (size_t)HALF_ * HID);
    tsplit1_k<<<dim3(VOC / 32, HID / 32), 256>>>(ow, HID, VOC, owh);
    bpack_k<<<2, 256>>>(sb, eb);

    // A operand for GEMM1: gathered embeddings, split fp16
    gsplit_k<<<TOK * 64 / 256, 256>>>(seq, embed, ah, al);

    // GEMM1: relu(e @ w1 + b1) -> h1 (fp16 hi/lo)   [65536 x 1024, K=512]
    mma_gemm<0><<<dim3(FF / 128, TOK / 128), 128, GSMEM>>>(
        TOK, FF, HID, ah, al, w1h, b1, nullptr, h1h, h1l, nullptr, nullptr);

    // GEMM2: x = h1 @ w2 + b2 + e  -> fp32          [65536 x 512, K=1024]
    mma_gemm<1><<<dim3(HID / 128, TOK / 128), 128, GSMEM>>>(
        TOK, HID, FF, h1h, h1l, w2h, b2, xb, nullptr, nullptr, seq, embed);

    // LayerNorm -> h (fp16 hi/lo)
    ln_split_k<<<TOK / 8, 256>>>(xb, lng, lnb, hh, hl);

    // GEMM3: k = h @ [sem|epi] + bias -> fp32       [65536 x 512, K=512]
    mma_gemm<2><<<dim3(HID / 128, TOK / 128), 128, GSMEM>>>(
        TOK, HID, HID, hh, hl, wph, bp, kb, nullptr, nullptr, nullptr, nullptr);

    // backward scan (norms fused, fp16 split fused) -> c
    scan_k<<<128, 32>>>(kb, cb, ch, cl);

    // GEMM4: out = c @ out_w + out_b                [64 x 32000, K=512]
    mma_gemm<2><<<dim3(VOC / 128, 1), 128, GSMEM>>>(
        BATCH, VOC, HID, ch, cl, owh, ob, out, nullptr, nullptr, nullptr, nullptr);
}

// round 10
// speedup vs baseline: 1.8264x; 1.8264x over previous
#include <cuda_runtime.h>
#include <cuda_fp16.h>
#include <cstdint>

// Problem constants
#define TOK   65536      // B*L
#define BATCH 64
#define SEQL  1024
#define HID   512
#define FF    1024
#define HALF_ 256
#define VOC   32000

typedef __half half_t;

__device__ __forceinline__ uint32_t smem_u32(const void* p) {
    uint32_t a;
    asm("{ .reg .u64 t; cvta.to.shared.u64 t, %1; cvt.u32.u64 %0, t; }" : "=r"(a) : "l"(p));
    return a;
}
#define SW128(o) ((o) ^ (((o) >> 3) & 0x70))

__device__ __forceinline__ void ldsm4(uint32_t* r, uint32_t a) {
    asm volatile("ldmatrix.sync.aligned.m8n8.x4.shared.b16 {%0,%1,%2,%3}, [%4];"
        : "=r"(r[0]), "=r"(r[1]), "=r"(r[2]), "=r"(r[3]) : "r"(a));
}
__device__ __forceinline__ void mma16816(float* c, const uint32_t* a, const uint32_t* b) {
    asm volatile("mma.sync.aligned.m16n8k16.row.col.f32.f16.f16.f32 "
        "{%0,%1,%2,%3}, {%4,%5,%6,%7}, {%8,%9}, {%0,%1,%2,%3};"
        : "+f"(c[0]), "+f"(c[1]), "+f"(c[2]), "+f"(c[3])
        : "r"(a[0]), "r"(a[1]), "r"(a[2]), "r"(a[3]), "r"(b[0]), "r"(b[1]));
}
__device__ __forceinline__ void cp16(uint32_t dst, const void* src, bool pred) {
    const int sz = pred ? 16 : 0;
    asm volatile("cp.async.cg.shared.global [%0], [%1], 16, %2;"
        :: "r"(dst), "l"(src), "r"(sz) : "memory");
}
#define CP_COMMIT() asm volatile("cp.async.commit_group;" ::: "memory")
template<int N>
__device__ __forceinline__ void cp_wait() {
    asm volatile("cp.async.wait_group %0;" :: "n"(N) : "memory");
}

__device__ __forceinline__ void split2h(float x, half_t& h, half_t& l) {
    h = __float2half_rn(x);
    l = __float2half_rn(x - __half2float(h));
}

// -------- scratch (device globals) --------
__device__ half_t g_ah[(size_t)TOK * HID],  g_al[(size_t)TOK * HID];
__device__ half_t g_h1h[(size_t)TOK * FF],  g_h1l[(size_t)TOK * FF];
__device__ half_t g_hh[(size_t)TOK * HID],  g_hl[(size_t)TOK * HID];
__device__ float  g_x[(size_t)TOK * HID];
__device__ float  g_k[(size_t)TOK * HID];
__device__ half_t g_w1h[(size_t)FF * HID];
__device__ half_t g_w2h[(size_t)HID * FF];
__device__ half_t g_wph[(size_t)HID * HID];
__device__ half_t g_owh[(size_t)VOC * HID];
__device__ float  g_bproj[HID];
__device__ float  g_c[BATCH * HID];
__device__ half_t g_ch[BATCH * HID], g_cl[BATCH * HID];

// ============================================================
// mma.sync fp16 2-pass GEMM, cp.async 4-stage pipeline.
// (Round-7 configuration: 256 threads, 8 warps, 64x32 warp tile.)
// C[M,N] = A[M,K] @ B^T;  A [M,K] K-major hi/lo fp16, B [N,K] single fp16.
// C = Ah*B + Al*B.
// A smem rows: 128B = [hi 64B | lo 64B]; B smem: two 64B rows per 128B
// line: off(n,k) = (n>>1)*128 + (n&1)*64 + k*2; SW128 swizzle everywhere.
// Stage = 16KB A + 8KB B = 24KB; 4 stages; one __syncthreads per chunk.
// EPI: 0 = relu(acc+bias) -> split fp16; 1 = acc+bias+embed[seq[m]] -> f32;
//      2 = acc+bias -> f32.
// ============================================================
#define ASTAGE 16384
#define GSTAGE 24576
#define NSTAGE 4
#define GSMEM  (NSTAGE * GSTAGE)

template<int EPI>
__global__ void __launch_bounds__(256, 2) mma_gemm(
    int Mrows, int N, int K,
    const half_t* __restrict__ Ah, const half_t* __restrict__ Al,
    const half_t* __restrict__ Bh,
    const float* __restrict__ bias,
    float* __restrict__ Cf, half_t* __restrict__ Chi, half_t* __restrict__ Clo,
    const int* __restrict__ seq, const float* __restrict__ embed)
{
    extern __shared__ __align__(1024) char smem[];
    const uint32_t sbase = smem_u32(smem);
    const int tid = threadIdx.x;
    const int bm = blockIdx.y * 128;
    const int bn = blockIdx.x * 128;
    const int wid = tid >> 5, lane = tid & 31;
    const int wm = (wid >> 2) * 64;     // warp row offset (0 / 64)
    const int wn = (wid & 3) * 32;      // warp col offset (0..96)
    const bool mguard = (Mrows & 127) != 0;

    // loader mapping: 2 threads per row, each 2x16B per half
    const int lrow = tid >> 1;
    const int lw = (tid & 1) * 2;
    const int am = bm + lrow;
    const bool av = !mguard || (am < Mrows);
    const size_t aoff = (size_t)(av ? am : 0) * K;
    const size_t boff = (size_t)(bn + lrow) * K;
    const uint32_t bline = (uint32_t)((lrow >> 1) * 128 + (lrow & 1) * 64);

    // A ldmatrix lane addressing (m16 x k16 per x4)
    const int a_mi = lane >> 3;
    const int a_row = (lane & 7) + (a_mi & 1) * 8;
    const int a_kb = (a_mi >> 1) * 16;
    // B ldmatrix lane addressing (2 n8 tiles x 2 k-halves per x4)
    const int b_g = lane >> 3;
    const int b_row = lane & 7;
    const int b_nt = b_g >> 1;
    const int b_kh = (b_g & 1) * 16;

    float c[16][4];
#pragma unroll
    for (int i = 0; i < 16; i++)
#pragma unroll
        for (int j = 0; j < 4; j++) c[i][j] = 0.f;

    const int NCH = K >> 5;

    auto load_stage = [&](int s, int k0) {
        const uint32_t sA = sbase + s * GSTAGE;
        const uint32_t sB = sA + ASTAGE;
#pragma unroll
        for (int it = 0; it < 2; it++) {
            const int word = lw + it;              // 0..3
            const uint32_t soh = SW128((uint32_t)(lrow * 128 + word * 16));
            const uint32_t sol = SW128((uint32_t)(lrow * 128 + 64 + word * 16));
            const size_t ko = (size_t)(k0 + word * 8);
            cp16(sA + soh, Ah + aoff + ko, av);
            cp16(sA + sol, Al + aoff + ko, av);
            cp16(sB + SW128(bline + word * 16), Bh + boff + ko, true);
        }
    };

    load_stage(0, 0);
    CP_COMMIT();
    load_stage(1, 32);
    CP_COMMIT();
    load_stage(2, 64);
    CP_COMMIT();

    int stage = 0;
    for (int ch = 0; ch < NCH; ch++) {
        cp_wait<2>();
        __syncthreads();
        if (ch + 3 < NCH) {
            int ns = stage + 3; if (ns >= NSTAGE) ns -= NSTAGE;
            load_stage(ns, (ch + 3) * 32);
        }
        CP_COMMIT();   // always commit (possibly empty) to keep accounting
        const uint32_t sAu = sbase + stage * GSTAGE;
        const uint32_t sBu = sAu + ASTAGE;
        // ---- compute: 2 k16 steps, 2 passes each ----
#pragma unroll
        for (int k16 = 0; k16 < 2; k16++) {
            const int kb = k16 * 32;
            uint32_t bfrag[2][4];
#pragma unroll
            for (int p = 0; p < 2; p++) {
                const int n = wn + (p * 2 + b_nt) * 8 + b_row;
                const uint32_t rb = (uint32_t)((n >> 1) * 128 + (n & 1) * 64);
                ldsm4(bfrag[p], sBu + SW128(rb + kb + b_kh));
            }
            uint32_t a[4][4];
#pragma unroll
            for (int mt = 0; mt < 4; mt++)
                ldsm4(a[mt], sAu + SW128((uint32_t)((wm + mt * 16 + a_row) * 128) + kb + a_kb));
#pragma unroll
            for (int mt = 0; mt < 4; mt++)
#pragma unroll
                for (int nt = 0; nt < 4; nt++)
                    mma16816(c[mt * 4 + nt], a[mt], &bfrag[nt >> 1][(nt & 1) * 2]);
            // lo(A) pass
#pragma unroll
            for (int mt = 0; mt < 4; mt++)
                ldsm4(a[mt], sAu + SW128((uint32_t)((wm + mt * 16 + a_row) * 128) + 64 + kb + a_kb));
#pragma unroll
            for (int mt = 0; mt < 4; mt++)
#pragma unroll
                for (int nt = 0; nt < 4; nt++)
                    mma16816(c[mt * 4 + nt], a[mt], &bfrag[nt >> 1][(nt & 1) * 2]);
        }
        if (++stage >= NSTAGE) stage = 0;
    }

    // ---- epilogue ----
    const int mrow = lane >> 2;
    const int mcol = (lane & 3) * 2;
#pragma unroll
    for (int mt = 0; mt < 4; mt++) {
        const int r0 = bm + wm + mt * 16 + mrow;
        const int r1 = r0 + 8;
        const bool v0 = !mguard || (r0 < Mrows);
        const bool v1 = !mguard || (r1 < Mrows);
        const float* e0 = nullptr;
        const float* e1 = nullptr;
        if (EPI == 1) {
            if (v0) e0 = embed + (size_t)seq[r0] * HID;
            if (v1) e1 = embed + (size_t)seq[r1] * HID;
        }
#pragma unroll
        for (int nt = 0; nt < 4; nt++) {
            const int col = bn + wn + nt * 8 + mcol;
            float* cc = c[mt * 4 + nt];
            const float b0v = bias[col], b1v = bias[col + 1];
            float x0 = cc[0] + b0v, x1 = cc[1] + b1v;
            float x2 = cc[2] + b0v, x3 = cc[3] + b1v;
            if (EPI == 0) {
                x0 = fmaxf(x0, 0.f); x1 = fmaxf(x1, 0.f);
                x2 = fmaxf(x2, 0.f); x3 = fmaxf(x3, 0.f);
                half_t h0, l0, h1, l1;
                if (v0) {
                    split2h(x0, h0, l0); split2h(x1, h1, l1);
                    __half2 ph; ph.x = h0; ph.y = h1;
                    __half2 pl; pl.x = l0; pl.y = l1;
                    *(__half2*)(Chi + (size_t)r0 * N + col) = ph;
                    *(__half2*)(Clo + (size_t)r0 * N + col) = pl;
                }
                if (v1) {
                    split2h(x2, h0, l0); split2h(x3, h1, l1);
                    __half2 ph; ph.x = h0; ph.y = h1;
                    __half2 pl; pl.x = l0; pl.y = l1;
                    *(__half2*)(Chi + (size_t)r1 * N + col) = ph;
                    *(__half2*)(Clo + (size_t)r1 * N + col) = pl;
                }
            } else {
                if (EPI == 1) {
                    if (v0) { x0 += e0[col]; x1 += e0[col + 1]; }
                    if (v1) { x2 += e1[col]; x3 += e1[col + 1]; }
                }
                if (v0) *(float2*)(Cf + (size_t)r0 * N + col) = make_float2(x0, x1);
                if (v1) *(float2*)(Cf + (size_t)r1 * N + col) = make_float2(x2, x3);
            }
        }
    }
}

// ============================================================
// gather + split:  Ahi/Alo[m] = split(embed[seq[m]])  (fp16)
// ============================================================
__global__ void __launch_bounds__(256) gsplit_k(const int* __restrict__ seq,
                                                const float* __restrict__ embed,
                                                half_t* __restrict__ hi, half_t* __restrict__ lo)
{
    const size_t idx = (size_t)blockIdx.x * 256 + threadIdx.x;   // TOK*64
    const int t = (int)(idx >> 6), c = (int)(idx & 63) * 8;
    const float* p = embed + (size_t)seq[t] * HID + c;
    float4 a = *(const float4*)p;
    float4 b = *(const float4*)(p + 4);
    float vv[8] = {a.x, a.y, a.z, a.w, b.x, b.y, b.z, b.w};
    const size_t ob = (size_t)t * HID + c;
#pragma unroll
    for (int j = 0; j < 8; j += 2) {
        half_t h0, l0, h1, l1;
        split2h(vv[j], h0, l0);
        split2h(vv[j + 1], h1, l1);
        __half2 ph; ph.x = h0; ph.y = h1;
        __half2 pl; pl.x = l0; pl.y = l1;
        *(__half2*)(hi + ob + j) = ph;
        *(__half2*)(lo + ob + j) = pl;
    }
}

// ============================================================
// Tiled transpose + round: W[K,N] fp32 -> out[N,K] single fp16.
// ============================================================
__global__ void __launch_bounds__(256) tsplit1_k(const float* __restrict__ W, int K, int N,
                                                 half_t* __restrict__ ht)
{
    __shared__ float t[32][33];
    const int tx = threadIdx.x & 31, ty = threadIdx.x >> 5;
    const int n0 = blockIdx.x * 32, k0 = blockIdx.y * 32;
#pragma unroll
    for (int i = 0; i < 4; i++)
        t[ty + 8 * i][tx] = W[(size_t)(k0 + ty + 8 * i) * N + n0 + tx];
    __syncthreads();
#pragma unroll
    for (int i = 0; i < 4; i++) {
        const size_t o = (size_t)(n0 + ty + 8 * i) * K + k0 + tx;
        ht[o] = __float2half_rn(t[tx][ty + 8 * i]);
    }
}

// ============================================================
// LayerNorm (warp per row) + split output to fp16 hi/lo.
// ============================================================
__global__ void __launch_bounds__(256) ln_split_k(const float* __restrict__ x,
                                                  const float* __restrict__ g,
                                                  const float* __restrict__ b,
                                                  half_t* __restrict__ hh, half_t* __restrict__ hl)
{
    const int row = blockIdx.x * 8 + (threadIdx.x >> 5);
    const int ln = threadIdx.x & 31;
    const float* xr = x + (size_t)row * HID + ln * 16;
    float v[16];
    *(float4*)&v[0]  = ((const float4*)xr)[0];
    *(float4*)&v[4]  = ((const float4*)xr)[1];
    *(float4*)&v[8]  = ((const float4*)xr)[2];
    *(float4*)&v[12] = ((const float4*)xr)[3];
    float s = 0.f;
#pragma unroll
    for (int j = 0; j < 16; j++) s += v[j];
#pragma unroll
    for (int o = 16; o; o >>= 1) s += __shfl_xor_sync(0xffffffffu, s, o);
    const float mean = s * (1.f / 512.f);
    float q = 0.f;
#pragma unroll
    for (int j = 0; j < 16; j++) { float d = v[j] - mean; q += d * d; }
#pragma unroll
    for (int o = 16; o; o >>= 1) q += __shfl_xor_sync(0xffffffffu, q, o);
    const float r = rsqrtf(q * (1.f / 512.f) + 1e-5f);
    const size_t ob = (size_t)row * HID + ln * 16;
#pragma unroll
    for (int j = 0; j < 16; j += 2) {
        const int c0 = ln * 16 + j;
        float y0 = (v[j] - mean) * r * g[c0] + b[c0];
        float y1 = (v[j + 1] - mean) * r * g[c0 + 1] + b[c0 + 1];
        half_t h0, l0, h1, l1;
        split2h(y0, h0, l0);
        split2h(y1, h1, l1);
        __half2 ph; ph.x = h0; ph.y = h1;
        __half2 pl; pl.x = l0; pl.y = l1;
        *(__half2*)(hh + ob + j) = ph;
        *(__half2*)(hl + ob + j) = pl;
    }
}

// ============================================================
__global__ void bpack_k(const float* __restrict__ sb, const float* __restrict__ eb)
{
    const int i = blockIdx.x * 256 + threadIdx.x;
    if (i < HID) g_bproj[i] = (i < HALF_) ? sb[i] : eb[i - HALF_];
}

// ============================================================
// Backward vector scan, 2 steps per iteration, inline norms,
// depth-2 row prefetch, fp32 + split-fp16 outputs.
// One warp per (batch, half) chain; 8 floats per lane.
//   s_t     = k_t . u_{t+1};  ws = w_t s;  us = ws / (||k_t||^2 + eps)
//   s_{t-1} = k_{t-1}.u_{t+1} - us_t (k_{t-1}.k_t)
// ============================================================
__global__ void __launch_bounds__(32) scan_k(const float* __restrict__ kall,
                                             float* __restrict__ cbuf,
                                             half_t* __restrict__ chh,
                                             half_t* __restrict__ chl)
{
    const int chain = blockIdx.x;
    const int b = chain >> 1, wh = chain & 1;
    const int ln = threadIdx.x;
    const float* base = kall + (size_t)b * SEQL * HID + wh * HALF_ + ln * 8;

#define LOADROW(dst, t) do { \
    float4 _a = *(const float4*)(base + (size_t)(t) * HID); \
    float4 _b = *(const float4*)(base + (size_t)(t) * HID + 4); \
    dst[0]=_a.x; dst[1]=_a.y; dst[2]=_a.z; dst[3]=_a.w; \
    dst[4]=_b.x; dst[5]=_b.y; dst[6]=_b.z; dst[7]=_b.w; } while (0)

    float u[8], acc[8], k0[8], k1[8], p0[8], p1[8];
    LOADROW(u, SEQL - 1);
#pragma unroll
    for (int j = 0; j < 8; j++) acc[j] = 0.f;

    // ---- single first step t = 1022 ----
    {
        float kc[8];
        LOADROW(kc, SEQL - 2);
        // issue next rows early
        LOADROW(k0, SEQL - 3);   // t=1021
        LOADROW(k1, SEQL - 4);   // t=1020
        LOADROW(p0, SEQL - 5);   // t=1019
        LOADROW(p1, SEQL - 6);   // t=1018
        float pa = 0.f, n0 = 0.f;
#pragma unroll
        for (int j = 0; j < 8; j++) { pa += kc[j] * u[j]; n0 += kc[j] * kc[j]; }
#pragma unroll
        for (int o = 16; o; o >>= 1) {
            pa += __shfl_xor_sync(0xffffffffu, pa, o);
            n0 += __shfl_xor_sync(0xffffffffu, n0, o);
        }
        const float w = wh ? (1023.f / 1024.f) : 1.f;
        const float ws = w * pa;
        const float us = ws / (n0 + 1e-6f);
#pragma unroll
        for (int j = 0; j < 8; j++) { acc[j] += ws * kc[j]; u[j] -= us * kc[j]; }
    }

    // ---- pair loop: t = 1021, 1019, ..., 1 (511 iterations) ----
    for (int t = SEQL - 3; t >= 1; t -= 2) {
        float q0[8] = {0, 0, 0, 0, 0, 0, 0, 0};
        float q1[8] = {0, 0, 0, 0, 0, 0, 0, 0};
        if (t >= 5) {
            LOADROW(q0, t - 4);
            LOADROW(q1, t - 5);
        }
        float pa = 0.f, pb = 0.f, pg = 0.f, n0 = 0.f, n1 = 0.f;
#pragma unroll
        for (int j = 0; j < 8; j++) {
            pa += k0[j] * u[j];
            pb += k1[j] * u[j];
            pg += k1[j] * k0[j];
            n0 += k0[j] * k0[j];
            n1 += k1[j] * k1[j];
        }
#pragma unroll
        for (int o = 16; o; o >>= 1) {
            pa += __shfl_xor_sync(0xffffffffu, pa, o);
            pb += __shfl_xor_sync(0xffffffffu, pb, o);
            pg += __shfl_xor_sync(0xffffffffu, pg, o);
            n0 += __shfl_xor_sync(0xffffffffu, n0, o);
            n1 += __shfl_xor_sync(0xffffffffu, n1, o);
        }
        const float inv1024 = 1.f / 1024.f;
        const float w0 = wh ? (float)(t + 1) * inv1024 : 1.f;
        const float w1 = wh ? (float)t * inv1024 : 1.f;
        const float id0 = 1.f / (n0 + 1e-6f);
        const float id1 = 1.f / (n1 + 1e-6f);
        const float ws0 = w0 * pa;
        const float us0 = ws0 * id0;
        const float s1 = pb - us0 * pg;
        const float ws1 = w1 * s1;
        const float us1 = ws1 * id1;
#pragma unroll
        for (int j = 0; j < 8; j++) {
            acc[j] += ws0 * k0[j] + ws1 * k1[j];
            u[j]   -= us0 * k0[j] + us1 * k1[j];
        }
        // rotate prefetch registers
#pragma unroll
        for (int j = 0; j < 8; j++) {
            k0[j] = p0[j]; k1[j] = p1[j];
            p0[j] = q0[j]; p1[j] = q1[j];
        }
    }

    const size_t ob = (size_t)b * HID + wh * HALF_ + ln * 8;
    *(float4*)(cbuf + ob)     = make_float4(acc[0], acc[1], acc[2], acc[3]);
    *(float4*)(cbuf + ob + 4) = make_float4(acc[4], acc[5], acc[6], acc[7]);
#pragma unroll
    for (int j = 0; j < 8; j += 2) {
        half_t h0, l0, h1, l1;
        split2h(acc[j], h0, l0);
        split2h(acc[j + 1], h1, l1);
        __half2 ph; ph.x = h0; ph.y = h1;
        __half2 pl; pl.x = l0; pl.y = l1;
        *(__half2*)(chh + ob + j) = ph;
        *(__half2*)(chl + ob + j) = pl;
    }
#undef LOADROW
}

// ============================================================
extern "C" void kernel_launch(void* const* d_in, const int* in_sizes, int n_in,
                              void* d_out, int out_size)
{
    const int*   seq   = (const int*)d_in[0];
    const float* embed = (const float*)d_in[1];
    const float* w1    = (const float*)d_in[2];
    const float* b1    = (const float*)d_in[3];
    const float* w2    = (const float*)d_in[4];
    const float* b2    = (const float*)d_in[5];
    const float* lng   = (const float*)d_in[6];
    const float* lnb   = (const float*)d_in[7];
    const float* sw    = (const float*)d_in[8];
    const float* sb    = (const float*)d_in[9];
    const float* ew    = (const float*)d_in[10];
    const float* eb    = (const float*)d_in[11];
    const float* ow    = (const float*)d_in[12];
    const float* ob    = (const float*)d_in[13];
    float* out = (float*)d_out;

    static bool init = false;
    static half_t *ah, *al, *h1h, *h1l, *hh, *hl, *w1h, *w2h, *wph, *owh, *ch, *cl;
    static float *xb, *kb, *bp, *cb;
    if (!init) {
        cudaGetSymbolAddress((void**)&ah,  g_ah);   cudaGetSymbolAddress((void**)&al,  g_al);
        cudaGetSymbolAddress((void**)&h1h, g_h1h);  cudaGetSymbolAddress((void**)&h1l, g_h1l);
        cudaGetSymbolAddress((void**)&hh,  g_hh);   cudaGetSymbolAddress((void**)&hl,  g_hl);
        cudaGetSymbolAddress((void**)&w1h, g_w1h);
        cudaGetSymbolAddress((void**)&w2h, g_w2h);
        cudaGetSymbolAddress((void**)&wph, g_wph);
        cudaGetSymbolAddress((void**)&owh, g_owh);
        cudaGetSymbolAddress((void**)&ch,  g_ch);   cudaGetSymbolAddress((void**)&cl,  g_cl);
        cudaGetSymbolAddress((void**)&xb,  g_x);
        cudaGetSymbolAddress((void**)&kb,  g_k);
        cudaGetSymbolAddress((void**)&bp,  g_bproj);
        cudaGetSymbolAddress((void**)&cb,  g_c);
        cudaFuncSetAttribute(mma_gemm<0>, cudaFuncAttributeMaxDynamicSharedMemorySize, GSMEM);
        cudaFuncSetAttribute(mma_gemm<1>, cudaFuncAttributeMaxDynamicSharedMemorySize, GSMEM);
        cudaFuncSetAttribute(mma_gemm<2>, cudaFuncAttributeMaxDynamicSharedMemorySize, GSMEM);
        init = true;
    }

    // weight transpose + fp16 round (B operands are [N,K] K-major, single fp16)
    tsplit1_k<<<dim3(FF / 32, HID / 32), 256>>>(w1, HID, FF, w1h);
    tsplit1_k<<<dim3(HID / 32, FF / 32), 256>>>(w2, FF, HID, w2h);
    tsplit1_k<<<dim3(HALF_ / 32, HID / 32), 256>>>(sw, HID, HALF_, wph);
    tsplit1_k<<<dim3(HALF_ / 32, HID / 32), 256>>>(ew, HID, HALF_, wph + (size_t)HALF_ * HID);
    tsplit1_k<<<dim3(VOC / 32, HID / 32), 256>>>(ow, HID, VOC, owh);
    bpack_k<<<2, 256>>>(sb, eb);

    // A operand for GEMM1: gathered embeddings, split fp16
    gsplit_k<<<TOK * 64 / 256, 256>>>(seq, embed, ah, al);

    // GEMM1: relu(e @ w1 + b1) -> h1 (fp16 hi/lo)   [65536 x 1024, K=512]
    mma_gemm<0><<<dim3(FF / 128, TOK / 128), 256, GSMEM>>>(
        TOK, FF, HID, ah, al, w1h, b1, nullptr, h1h, h1l, nullptr, nullptr);

    // GEMM2: x = h1 @ w2 + b2 + e  -> fp32          [65536 x 512, K=1024]
    mma_gemm<1><<<dim3(HID / 128, TOK / 128), 256, GSMEM>>>(
        TOK, HID, FF, h1h, h1l, w2h, b2, xb, nullptr, nullptr, seq, embed);

    // LayerNorm -> h (fp16 hi/lo)
    ln_split_k<<<TOK / 8, 256>>>(xb, lng, lnb, hh, hl);

    // GEMM3: k = h @ [sem|epi] + bias -> fp32       [65536 x 512, K=512]
    mma_gemm<2><<<dim3(HID / 128, TOK / 128), 256, GSMEM>>>(
        TOK, HID, HID, hh, hl, wph, bp, kb, nullptr, nullptr, nullptr, nullptr);

    // backward scan (norms fused, fp16 split fused) -> c
    scan_k<<<128, 32>>>(kb, cb, ch, cl);

    // GEMM4: out = c @ out_w + out_b                [64 x 32000, K=512]
    mma_gemm<2><<<dim3(VOC / 128, 1), 256, GSMEM>>>(
        BATCH, VOC, HID, ch, cl, owh, ob, out, nullptr, nullptr, nullptr, nullptr);
}

// round 11
// speedup vs baseline: 1.8523x; 1.0142x over previous
#include <cuda_runtime.h>
#include <cuda_fp16.h>
#include <cstdint>

// Problem constants
#define TOK   65536      // B*L
#define BATCH 64
#define SEQL  1024
#define HID   512
#define FF    1024
#define HALF_ 256
#define VOC   32000

typedef __half half_t;

__device__ __forceinline__ uint32_t smem_u32(const void* p) {
    uint32_t a;
    asm("{ .reg .u64 t; cvta.to.shared.u64 t, %1; cvt.u32.u64 %0, t; }" : "=r"(a) : "l"(p));
    return a;
}
#define SW128(o) ((o) ^ (((o) >> 3) & 0x70))

__device__ __forceinline__ void ldsm4(uint32_t* r, uint32_t a) {
    asm volatile("ldmatrix.sync.aligned.m8n8.x4.shared.b16 {%0,%1,%2,%3}, [%4];"
        : "=r"(r[0]), "=r"(r[1]), "=r"(r[2]), "=r"(r[3]) : "r"(a));
}
__device__ __forceinline__ void mma16816(float* c, const uint32_t* a, const uint32_t* b) {
    asm volatile("mma.sync.aligned.m16n8k16.row.col.f32.f16.f16.f32 "
        "{%0,%1,%2,%3}, {%4,%5,%6,%7}, {%8,%9}, {%0,%1,%2,%3};"
        : "+f"(c[0]), "+f"(c[1]), "+f"(c[2]), "+f"(c[3])
        : "r"(a[0]), "r"(a[1]), "r"(a[2]), "r"(a[3]), "r"(b[0]), "r"(b[1]));
}
__device__ __forceinline__ void cp16(uint32_t dst, const void* src, bool pred) {
    const int sz = pred ? 16 : 0;
    asm volatile("cp.async.cg.shared.global [%0], [%1], 16, %2;"
        :: "r"(dst), "l"(src), "r"(sz) : "memory");
}
#define CP_COMMIT() asm volatile("cp.async.commit_group;" ::: "memory")
template<int N>
__device__ __forceinline__ void cp_wait() {
    asm volatile("cp.async.wait_group %0;" :: "n"(N) : "memory");
}

__device__ __forceinline__ void split2h(float x, half_t& h, half_t& l) {
    h = __float2half_rn(x);
    l = __float2half_rn(x - __half2float(h));
}

// -------- scratch (device globals) --------
__device__ half_t g_ah[(size_t)TOK * HID],  g_al[(size_t)TOK * HID];
__device__ half_t g_h1h[(size_t)TOK * FF],  g_h1l[(size_t)TOK * FF];
__device__ half_t g_hh[(size_t)TOK * HID],  g_hl[(size_t)TOK * HID];
__device__ float  g_x[(size_t)TOK * HID];
__device__ float  g_k[(size_t)TOK * HID];
__device__ half_t g_w1h[(size_t)FF * HID];
__device__ half_t g_w2h[(size_t)HID * FF];
__device__ half_t g_wph[(size_t)HID * HID];
__device__ half_t g_owh[(size_t)VOC * HID];
__device__ float  g_bproj[HID];
__device__ float  g_c[BATCH * HID];
__device__ half_t g_ch[BATCH * HID], g_cl[BATCH * HID];

// ============================================================
// mma.sync fp16 2-pass GEMM, cp.async 4-stage pipeline.
// Warp tile 32x64 (crossbar-optimal: 64KB smem reads per CTA chunk vs 80KB
// for 64x32, same 64 accumulator regs/thread).
// C[M,N] = A[M,K] @ B^T;  A [M,K] K-major hi/lo fp16, B [N,K] single fp16.
// C = Ah*B + Al*B.
// 128x128 CTA tile, BK=32, 256 threads (8 warps: 4 row groups x 2 col groups).
// A smem rows: 128B = [hi 64B | lo 64B]; B smem: two 64B rows per 128B
// line: off(n,k) = (n>>1)*128 + (n&1)*64 + k*2; SW128 swizzle everywhere.
// Stage = 16KB A + 8KB B = 24KB; 4 stages; one __syncthreads per chunk.
// EPI: 0 = relu(acc+bias) -> split fp16; 1 = acc+bias+embed[seq[m]] -> f32;
//      2 = acc+bias -> f32.
// ============================================================
#define ASTAGE 16384
#define GSTAGE 24576
#define NSTAGE 4
#define GSMEM  (NSTAGE * GSTAGE)

template<int EPI>
__global__ void __launch_bounds__(256, 2) mma_gemm(
    int Mrows, int N, int K,
    const half_t* __restrict__ Ah, const half_t* __restrict__ Al,
    const half_t* __restrict__ Bh,
    const float* __restrict__ bias,
    float* __restrict__ Cf, half_t* __restrict__ Chi, half_t* __restrict__ Clo,
    const int* __restrict__ seq, const float* __restrict__ embed)
{
    extern __shared__ __align__(1024) char smem[];
    const uint32_t sbase = smem_u32(smem);
    const int tid = threadIdx.x;
    const int bm = blockIdx.y * 128;
    const int bn = blockIdx.x * 128;
    const int wid = tid >> 5, lane = tid & 31;
    const int wm = (wid & 3) * 32;      // warp row offset (0..96)
    const int wn = (wid >> 2) * 64;     // warp col offset (0 / 64)
    const bool mguard = (Mrows & 127) != 0;

    // loader mapping: 2 threads per row, each 2x16B per half
    const int lrow = tid >> 1;
    const int lw = (tid & 1) * 2;
    const int am = bm + lrow;
    const bool av = !mguard || (am < Mrows);
    const size_t aoff = (size_t)(av ? am : 0) * K;
    const size_t boff = (size_t)(bn + lrow) * K;
    const uint32_t bline = (uint32_t)((lrow >> 1) * 128 + (lrow & 1) * 64);

    // A ldmatrix lane addressing (m16 x k16 per x4)
    const int a_mi = lane >> 3;
    const int a_row = (lane & 7) + (a_mi & 1) * 8;
    const int a_kb = (a_mi >> 1) * 16;
    // B ldmatrix lane addressing (2 n8 tiles x 2 k-halves per x4)
    const int b_g = lane >> 3;
    const int b_row = lane & 7;
    const int b_nt = b_g >> 1;
    const int b_kh = (b_g & 1) * 16;

    float c[16][4];                     // [mt*8 + nt][4], mt<2, nt<8
#pragma unroll
    for (int i = 0; i < 16; i++)
#pragma unroll
        for (int j = 0; j < 4; j++) c[i][j] = 0.f;

    const int NCH = K >> 5;

    auto load_stage = [&](int s, int k0) {
        const uint32_t sA = sbase + s * GSTAGE;
        const uint32_t sB = sA + ASTAGE;
#pragma unroll
        for (int it = 0; it < 2; it++) {
            const int word = lw + it;              // 0..3
            const uint32_t soh = SW128((uint32_t)(lrow * 128 + word * 16));
            const uint32_t sol = SW128((uint32_t)(lrow * 128 + 64 + word * 16));
            const size_t ko = (size_t)(k0 + word * 8);
            cp16(sA + soh, Ah + aoff + ko, av);
            cp16(sA + sol, Al + aoff + ko, av);
            cp16(sB + SW128(bline + word * 16), Bh + boff + ko, true);
        }
    };

    load_stage(0, 0);
    CP_COMMIT();
    load_stage(1, 32);
    CP_COMMIT();
    load_stage(2, 64);
    CP_COMMIT();

    int stage = 0;
    for (int ch = 0; ch < NCH; ch++) {
        cp_wait<2>();
        __syncthreads();
        if (ch + 3 < NCH) {
            int ns = stage + 3; if (ns >= NSTAGE) ns -= NSTAGE;
            load_stage(ns, (ch + 3) * 32);
        }
        CP_COMMIT();   // always commit (possibly empty) to keep accounting
        const uint32_t sAu = sbase + stage * GSTAGE;
        const uint32_t sBu = sAu + ASTAGE;
        // ---- compute: 2 k16 steps, 2 passes each ----
#pragma unroll
        for (int k16 = 0; k16 < 2; k16++) {
            const int kb = k16 * 32;
            uint32_t bfrag[4][4];       // 8 n8 tiles (64 cols)
#pragma unroll
            for (int p = 0; p < 4; p++) {
                const int n = wn + (p * 2 + b_nt) * 8 + b_row;
                const uint32_t rb = (uint32_t)((n >> 1) * 128 + (n & 1) * 64);
                ldsm4(bfrag[p], sBu + SW128(rb + kb + b_kh));
            }
            uint32_t a[2][4];
#pragma unroll
            for (int mt = 0; mt < 2; mt++)
                ldsm4(a[mt], sAu + SW128((uint32_t)((wm + mt * 16 + a_row) * 128) + kb + a_kb));
#pragma unroll
            for (int mt = 0; mt < 2; mt++)
#pragma unroll
                for (int nt = 0; nt < 8; nt++)
                    mma16816(c[mt * 8 + nt], a[mt], &bfrag[nt >> 1][(nt & 1) * 2]);
            // lo(A) pass
#pragma unroll
            for (int mt = 0; mt < 2; mt++)
                ldsm4(a[mt], sAu + SW128((uint32_t)((wm + mt * 16 + a_row) * 128) + 64 + kb + a_kb));
#pragma unroll
            for (int mt = 0; mt < 2; mt++)
#pragma unroll
                for (int nt = 0; nt < 8; nt++)
                    mma16816(c[mt * 8 + nt], a[mt], &bfrag[nt >> 1][(nt & 1) * 2]);
        }
        if (++stage >= NSTAGE) stage = 0;
    }

    // ---- epilogue ----
    const int mrow = lane >> 2;
    const int mcol = (lane & 3) * 2;
#pragma unroll
    for (int mt = 0; mt < 2; mt++) {
        const int r0 = bm + wm + mt * 16 + mrow;
        const int r1 = r0 + 8;
        const bool v0 = !mguard || (r0 < Mrows);
        const bool v1 = !mguard || (r1 < Mrows);
        const float* e0 = nullptr;
        const float* e1 = nullptr;
        if (EPI == 1) {
            if (v0) e0 = embed + (size_t)seq[r0] * HID;
            if (v1) e1 = embed + (size_t)seq[r1] * HID;
        }
#pragma unroll
        for (int nt = 0; nt < 8; nt++) {
            const int col = bn + wn + nt * 8 + mcol;
            float* cc = c[mt * 8 + nt];
            const float b0v = bias[col], b1v = bias[col + 1];
            float x0 = cc[0] + b0v, x1 = cc[1] + b1v;
            float x2 = cc[2] + b0v, x3 = cc[3] + b1v;
            if (EPI == 0) {
                x0 = fmaxf(x0, 0.f); x1 = fmaxf(x1, 0.f);
                x2 = fmaxf(x2, 0.f); x3 = fmaxf(x3, 0.f);
                half_t h0, l0, h1, l1;
                if (v0) {
                    split2h(x0, h0, l0); split2h(x1, h1, l1);
                    __half2 ph; ph.x = h0; ph.y = h1;
                    __half2 pl; pl.x = l0; pl.y = l1;
                    *(__half2*)(Chi + (size_t)r0 * N + col) = ph;
                    *(__half2*)(Clo + (size_t)r0 * N + col) = pl;
                }
                if (v1) {
                    split2h(x2, h0, l0); split2h(x3, h1, l1);
                    __half2 ph; ph.x = h0; ph.y = h1;
                    __half2 pl; pl.x = l0; pl.y = l1;
                    *(__half2*)(Chi + (size_t)r1 * N + col) = ph;
                    *(__half2*)(Clo + (size_t)r1 * N + col) = pl;
                }
            } else {
                if (EPI == 1) {
                    if (v0) { x0 += e0[col]; x1 += e0[col + 1]; }
                    if (v1) { x2 += e1[col]; x3 += e1[col + 1]; }
                }
                if (v0) *(float2*)(Cf + (size_t)r0 * N + col) = make_float2(x0, x1);
                if (v1) *(float2*)(Cf + (size_t)r1 * N + col) = make_float2(x2, x3);
            }
        }
    }
}

// ============================================================
// gather + split:  Ahi/Alo[m] = split(embed[seq[m]])  (fp16)
// ============================================================
__global__ void __launch_bounds__(256) gsplit_k(const int* __restrict__ seq,
                                                const float* __restrict__ embed,
                                                half_t* __restrict__ hi, half_t* __restrict__ lo)
{
    const size_t idx = (size_t)blockIdx.x * 256 + threadIdx.x;   // TOK*64
    const int t = (int)(idx >> 6), c = (int)(idx & 63) * 8;
    const float* p = embed + (size_t)seq[t] * HID + c;
    float4 a = *(const float4*)p;
    float4 b = *(const float4*)(p + 4);
    float vv[8] = {a.x, a.y, a.z, a.w, b.x, b.y, b.z, b.w};
    const size_t ob = (size_t)t * HID + c;
#pragma unroll
    for (int j = 0; j < 8; j += 2) {
        half_t h0, l0, h1, l1;
        split2h(vv[j], h0, l0);
        split2h(vv[j + 1], h1, l1);
        __half2 ph; ph.x = h0; ph.y = h1;
        __half2 pl; pl.x = l0; pl.y = l1;
        *(__half2*)(hi + ob + j) = ph;
        *(__half2*)(lo + ob + j) = pl;
    }
}

// ============================================================
// Tiled transpose + round: W[K,N] fp32 -> out[N,K] single fp16.
// ============================================================
__global__ void __launch_bounds__(256) tsplit1_k(const float* __restrict__ W, int K, int N,
                                                 half_t* __restrict__ ht)
{
    __shared__ float t[32][33];
    const int tx = threadIdx.x & 31, ty = threadIdx.x >> 5;
    const int n0 = blockIdx.x * 32, k0 = blockIdx.y * 32;
#pragma unroll
    for (int i = 0; i < 4; i++)
        t[ty + 8 * i][tx] = W[(size_t)(k0 + ty + 8 * i) * N + n0 + tx];
    __syncthreads();
#pragma unroll
    for (int i = 0; i < 4; i++) {
        const size_t o = (size_t)(n0 + ty + 8 * i) * K + k0 + tx;
        ht[o] = __float2half_rn(t[tx][ty + 8 * i]);
    }
}

// ============================================================
// LayerNorm (warp per row) + split output to fp16 hi/lo.
// ============================================================
__global__ void __launch_bounds__(256) ln_split_k(const float* __restrict__ x,
                                                  const float* __restrict__ g,
                                                  const float* __restrict__ b,
                                                  half_t* __restrict__ hh, half_t* __restrict__ hl)
{
    const int row = blockIdx.x * 8 + (threadIdx.x >> 5);
    const int ln = threadIdx.x & 31;
    const float* xr = x + (size_t)row * HID + ln * 16;
    float v[16];
    *(float4*)&v[0]  = ((const float4*)xr)[0];
    *(float4*)&v[4]  = ((const float4*)xr)[1];
    *(float4*)&v[8]  = ((const float4*)xr)[2];
    *(float4*)&v[12] = ((const float4*)xr)[3];
    float s = 0.f;
#pragma unroll
    for (int j = 0; j < 16; j++) s += v[j];
#pragma unroll
    for (int o = 16; o; o >>= 1) s += __shfl_xor_sync(0xffffffffu, s, o);
    const float mean = s * (1.f / 512.f);
    float q = 0.f;
#pragma unroll
    for (int j = 0; j < 16; j++) { float d = v[j] - mean; q += d * d; }
#pragma unroll
    for (int o = 16; o; o >>= 1) q += __shfl_xor_sync(0xffffffffu, q, o);
    const float r = rsqrtf(q * (1.f / 512.f) + 1e-5f);
    const size_t ob = (size_t)row * HID + ln * 16;
#pragma unroll
    for (int j = 0; j < 16; j += 2) {
        const int c0 = ln * 16 + j;
        float y0 = (v[j] - mean) * r * g[c0] + b[c0];
        float y1 = (v[j + 1] - mean) * r * g[c0 + 1] + b[c0 + 1];
        half_t h0, l0, h1, l1;
        split2h(y0, h0, l0);
        split2h(y1, h1, l1);
        __half2 ph; ph.x = h0; ph.y = h1;
        __half2 pl; pl.x = l0; pl.y = l1;
        *(__half2*)(hh + ob + j) = ph;
        *(__half2*)(hl + ob + j) = pl;
    }
}

// ============================================================
__global__ void bpack_k(const float* __restrict__ sb, const float* __restrict__ eb)
{
    const int i = blockIdx.x * 256 + threadIdx.x;
    if (i < HID) g_bproj[i] = (i < HALF_) ? sb[i] : eb[i - HALF_];
}

// ============================================================
// Backward vector scan, 2 steps per iteration, inline norms,
// depth-2 row prefetch, fp32 + split-fp16 outputs.
// ============================================================
__global__ void __launch_bounds__(32) scan_k(const float* __restrict__ kall,
                                             float* __restrict__ cbuf,
                                             half_t* __restrict__ chh,
                                             half_t* __restrict__ chl)
{
    const int chain = blockIdx.x;
    const int b = chain >> 1, wh = chain & 1;
    const int ln = threadIdx.x;
    const float* base = kall + (size_t)b * SEQL * HID + wh * HALF_ + ln * 8;

#define LOADROW(dst, t) do { \
    float4 _a = *(const float4*)(base + (size_t)(t) * HID); \
    float4 _b = *(const float4*)(base + (size_t)(t) * HID + 4); \
    dst[0]=_a.x; dst[1]=_a.y; dst[2]=_a.z; dst[3]=_a.w; \
    dst[4]=_b.x; dst[5]=_b.y; dst[6]=_b.z; dst[7]=_b.w; } while (0)

    float u[8], acc[8], k0[8], k1[8], p0[8], p1[8];
    LOADROW(u, SEQL - 1);
#pragma unroll
    for (int j = 0; j < 8; j++) acc[j] = 0.f;

    // ---- single first step t = 1022 ----
    {
        float kc[8];
        LOADROW(kc, SEQL - 2);
        LOADROW(k0, SEQL - 3);   // t=1021
        LOADROW(k1, SEQL - 4);   // t=1020
        LOADROW(p0, SEQL - 5);   // t=1019
        LOADROW(p1, SEQL - 6);   // t=1018
        float pa = 0.f, n0 = 0.f;
#pragma unroll
        for (int j = 0; j < 8; j++) { pa += kc[j] * u[j]; n0 += kc[j] * kc[j]; }
#pragma unroll
        for (int o = 16; o; o >>= 1) {
            pa += __shfl_xor_sync(0xffffffffu, pa, o);
            n0 += __shfl_xor_sync(0xffffffffu, n0, o);
        }
        const float w = wh ? (1023.f / 1024.f) : 1.f;
        const float ws = w * pa;
        const float us = ws / (n0 + 1e-6f);
#pragma unroll
        for (int j = 0; j < 8; j++) { acc[j] += ws * kc[j]; u[j] -= us * kc[j]; }
    }

    // ---- pair loop: t = 1021, 1019, ..., 1 (511 iterations) ----
    for (int t = SEQL - 3; t >= 1; t -= 2) {
        float q0[8] = {0, 0, 0, 0, 0, 0, 0, 0};
        float q1[8] = {0, 0, 0, 0, 0, 0, 0, 0};
        if (t >= 5) {
            LOADROW(q0, t - 4);
            LOADROW(q1, t - 5);
        }
        float pa = 0.f, pb = 0.f, pg = 0.f, n0 = 0.f, n1 = 0.f;
#pragma unroll
        for (int j = 0; j < 8; j++) {
            pa += k0[j] * u[j];
            pb += k1[j] * u[j];
            pg += k1[j] * k0[j];
            n0 += k0[j] * k0[j];
            n1 += k1[j] * k1[j];
        }
#pragma unroll
        for (int o = 16; o; o >>= 1) {
            pa += __shfl_xor_sync(0xffffffffu, pa, o);
            pb += __shfl_xor_sync(0xffffffffu, pb, o);
            pg += __shfl_xor_sync(0xffffffffu, pg, o);
            n0 += __shfl_xor_sync(0xffffffffu, n0, o);
            n1 += __shfl_xor_sync(0xffffffffu, n1, o);
        }
        const float inv1024 = 1.f / 1024.f;
        const float w0 = wh ? (float)(t + 1) * inv1024 : 1.f;
        const float w1 = wh ? (float)t * inv1024 : 1.f;
        const float id0 = 1.f / (n0 + 1e-6f);
        const float id1 = 1.f / (n1 + 1e-6f);
        const float ws0 = w0 * pa;
        const float us0 = ws0 * id0;
        const float s1 = pb - us0 * pg;
        const float ws1 = w1 * s1;
        const float us1 = ws1 * id1;
#pragma unroll
        for (int j = 0; j < 8; j++) {
            acc[j] += ws0 * k0[j] + ws1 * k1[j];
            u[j]   -= us0 * k0[j] + us1 * k1[j];
        }
#pragma unroll
        for (int j = 0; j < 8; j++) {
            k0[j] = p0[j]; k1[j] = p1[j];
            p0[j] = q0[j]; p1[j] = q1[j];
        }
    }

    const size_t ob = (size_t)b * HID + wh * HALF_ + ln * 8;
    *(float4*)(cbuf + ob)     = make_float4(acc[0], acc[1], acc[2], acc[3]);
    *(float4*)(cbuf + ob + 4) = make_float4(acc[4], acc[5], acc[6], acc[7]);
#pragma unroll
    for (int j = 0; j < 8; j += 2) {
        half_t h0, l0, h1, l1;
        split2h(acc[j], h0, l0);
        split2h(acc[j + 1], h1, l1);
        __half2 ph; ph.x = h0; ph.y = h1;
        __half2 pl; pl.x = l0; pl.y = l1;
        *(__half2*)(chh + ob + j) = ph;
        *(__half2*)(chl + ob + j) = pl;
    }
#undef LOADROW
}

// ============================================================
extern "C" void kernel_launch(void* const* d_in, const int* in_sizes, int n_in,
                              void* d_out, int out_size)
{
    const int*   seq   = (const int*)d_in[0];
    const float* embed = (const float*)d_in[1];
    const float* w1    = (const float*)d_in[2];
    const float* b1    = (const float*)d_in[3];
    const float* w2    = (const float*)d_in[4];
    const float* b2    = (const float*)d_in[5];
    const float* lng   = (const float*)d_in[6];
    const float* lnb   = (const float*)d_in[7];
    const float* sw    = (const float*)d_in[8];
    const float* sb    = (const float*)d_in[9];
    const float* ew    = (const float*)d_in[10];
    const float* eb    = (const float*)d_in[11];
    const float* ow    = (const float*)d_in[12];
    const float* ob    = (const float*)d_in[13];
    float* out = (float*)d_out;

    static bool init = false;
    static half_t *ah, *al, *h1h, *h1l, *hh, *hl, *w1h, *w2h, *wph, *owh, *ch, *cl;
    static float *xb, *kb, *bp, *cb;
    if (!init) {
        cudaGetSymbolAddress((void**)&ah,  g_ah);   cudaGetSymbolAddress((void**)&al,  g_al);
        cudaGetSymbolAddress((void**)&h1h, g_h1h);  cudaGetSymbolAddress((void**)&h1l, g_h1l);
        cudaGetSymbolAddress((void**)&hh,  g_hh);   cudaGetSymbolAddress((void**)&hl,  g_hl);
        cudaGetSymbolAddress((void**)&w1h, g_w1h);
        cudaGetSymbolAddress((void**)&w2h, g_w2h);
        cudaGetSymbolAddress((void**)&wph, g_wph);
        cudaGetSymbolAddress((void**)&owh, g_owh);
        cudaGetSymbolAddress((void**)&ch,  g_ch);   cudaGetSymbolAddress((void**)&cl,  g_cl);
        cudaGetSymbolAddress((void**)&xb,  g_x);
        cudaGetSymbolAddress((void**)&kb,  g_k);
        cudaGetSymbolAddress((void**)&bp,  g_bproj);
        cudaGetSymbolAddress((void**)&cb,  g_c);
        cudaFuncSetAttribute(mma_gemm<0>, cudaFuncAttributeMaxDynamicSharedMemorySize, GSMEM);
        cudaFuncSetAttribute(mma_gemm<1>, cudaFuncAttributeMaxDynamicSharedMemorySize, GSMEM);
        cudaFuncSetAttribute(mma_gemm<2>, cudaFuncAttributeMaxDynamicSharedMemorySize, GSMEM);
        init = true;
    }

    // weight transpose + fp16 round (B operands are [N,K] K-major, single fp16)
    tsplit1_k<<<dim3(FF / 32, HID / 32), 256>>>(w1, HID, FF, w1h);
    tsplit1_k<<<dim3(HID / 32, FF / 32), 256>>>(w2, FF, HID, w2h);
    tsplit1_k<<<dim3(HALF_ / 32, HID / 32), 256>>>(sw, HID, HALF_, wph);
    tsplit1_k<<<dim3(HALF_ / 32, HID / 32), 256>>>(ew, HID, HALF_, wph + (size_t)HALF_ * HID);
    tsplit1_k<<<dim3(VOC / 32, HID / 32), 256>>>(ow, HID, VOC, owh);
    bpack_k<<<2, 256>>>(sb, eb);

    // A operand for GEMM1: gathered embeddings, split fp16
    gsplit_k<<<TOK * 64 / 256, 256>>>(seq, embed, ah, al);

    // GEMM1: relu(e @ w1 + b1) -> h1 (fp16 hi/lo)   [65536 x 1024, K=512]
    mma_gemm<0><<<dim3(FF / 128, TOK / 128), 256, GSMEM>>>(
        TOK, FF, HID, ah, al, w1h, b1, nullptr, h1h, h1l, nullptr, nullptr);

    // GEMM2: x = h1 @ w2 + b2 + e  -> fp32          [65536 x 512, K=1024]
    mma_gemm<1><<<dim3(HID / 128, TOK / 128), 256, GSMEM>>>(
        TOK, HID, FF, h1h, h1l, w2h, b2, xb, nullptr, nullptr, seq, embed);

    // LayerNorm -> h (fp16 hi/lo)
    ln_split_k<<<TOK / 8, 256>>>(xb, lng, lnb, hh, hl);

    // GEMM3: k = h @ [sem|epi] + bias -> fp32       [65536 x 512, K=512]
    mma_gemm<2><<<dim3(HID / 128, TOK / 128), 256, GSMEM>>>(
        TOK, HID, HID, hh, hl, wph, bp, kb, nullptr, nullptr, nullptr, nullptr);

    // backward scan (norms fused, fp16 split fused) -> c
    scan_k<<<128, 32>>>(kb, cb, ch, cl);

    // GEMM4: out = c @ out_w + out_b                [64 x 32000, K=512]
    mma_gemm<2><<<dim3(VOC / 128, 1), 256, GSMEM>>>(
        BATCH, VOC, HID, ch, cl, owh, ob, out, nullptr, nullptr, nullptr, nullptr);
}

// round 14
// speedup vs baseline: 2.6653x; 1.4389x over previous
#include <cuda_runtime.h>
#include <cuda_fp16.h>
#include <cstdint>

// Problem constants
#define TOK   65536      // B*L
#define BATCH 64
#define SEQL  1024
#define HID   512
#define FF    1024
#define HALF_ 256
#define VOC   32000

typedef __half half_t;

__device__ __forceinline__ uint32_t smem_u32(const void* p) {
    uint32_t a;
    asm("{ .reg .u64 t; cvta.to.shared.u64 t, %1; cvt.u32.u64 %0, t; }" : "=r"(a) : "l"(p));
    return a;
}
#define SW128(o) ((o) ^ (((o) >> 3) & 0x70))

__device__ __forceinline__ void ldsm4(uint32_t* r, uint32_t a) {
    asm volatile("ldmatrix.sync.aligned.m8n8.x4.shared.b16 {%0,%1,%2,%3}, [%4];"
        : "=r"(r[0]), "=r"(r[1]), "=r"(r[2]), "=r"(r[3]) : "r"(a));
}
__device__ __forceinline__ void mma16816(float* c, const uint32_t* a, const uint32_t* b) {
    asm volatile("mma.sync.aligned.m16n8k16.row.col.f32.f16.f16.f32 "
        "{%0,%1,%2,%3}, {%4,%5,%6,%7}, {%8,%9}, {%0,%1,%2,%3};"
        : "+f"(c[0]), "+f"(c[1]), "+f"(c[2]), "+f"(c[3])
        : "r"(a[0]), "r"(a[1]), "r"(a[2]), "r"(a[3]), "r"(b[0]), "r"(b[1]));
}
__device__ __forceinline__ void cp16(uint32_t dst, const void* src, bool pred) {
    const int sz = pred ? 16 : 0;
    asm volatile("cp.async.cg.shared.global [%0], [%1], 16, %2;"
        :: "r"(dst), "l"(src), "r"(sz) : "memory");
}
#define CP_COMMIT() asm volatile("cp.async.commit_group;" ::: "memory")
template<int N>
__device__ __forceinline__ void cp_wait() {
    asm volatile("cp.async.wait_group %0;" :: "n"(N) : "memory");
}

__device__ __forceinline__ void split2h(float x, half_t& h, half_t& l) {
    h = __float2half_rn(x);
    l = __float2half_rn(x - __half2float(h));
}

// -------- scratch (device globals) --------
__device__ half_t g_ah[(size_t)TOK * HID];
__device__ half_t g_h1h[(size_t)TOK * FF];
__device__ half_t g_hh[(size_t)TOK * HID];
__device__ float  g_x[(size_t)TOK * HID];
__device__ float  g_k[(size_t)TOK * HID];
__device__ half_t g_w1h[(size_t)FF * HID];
__device__ half_t g_w2h[(size_t)HID * FF];
__device__ half_t g_wph[(size_t)HID * HID];
__device__ half_t g_owh[(size_t)VOC * HID];
__device__ float  g_bproj[HID];
__device__ float  g_c[BATCH * HID];
__device__ half_t g_ch[BATCH * HID], g_cl[BATCH * HID];

// ============================================================
// mma.sync fp16 GEMM, cp.async 4-stage pipeline.
// PASSES=1: C = A*B (A single fp16).  PASSES=2: C = Ah*B + Al*B.
// C[M,N] = A[M,K] @ B^T;  A [M,K] K-major fp16 (hi + optional lo),
// B [N,K] K-major single fp16.
// 128x128 CTA tile, BK=32, 256 threads (8 warps, 32x64 warp tile).
// A smem rows: 128B = [hi 64B | lo 64B] (lo unused when PASSES=1);
// B smem: two 64B rows per 128B line: off(n,k) = (n>>1)*128+(n&1)*64+k*2.
// SW128 swizzle everywhere. Stage 24KB; 4 stages; one sync per chunk.
// EPI: 0 = relu(acc+bias) -> fp16 (Chi only); 1 = acc+bias+embed[seq[m]] -> f32;
//      2 = acc+bias -> f32.
// ============================================================
#define ASTAGE 16384
#define GSTAGE 24576
#define NSTAGE 4
#define GSMEM  (NSTAGE * GSTAGE)

template<int EPI, int PASSES>
__global__ void __launch_bounds__(256, 2) mma_gemm(
    int Mrows, int N, int K,
    const half_t* __restrict__ Ah, const half_t* __restrict__ Al,
    const half_t* __restrict__ Bh,
    const float* __restrict__ bias,
    float* __restrict__ Cf, half_t* __restrict__ Chi,
    const int* __restrict__ seq, const float* __restrict__ embed)
{
    extern __shared__ __align__(1024) char smem[];
    const uint32_t sbase = smem_u32(smem);
    const int tid = threadIdx.x;
    const int bm = blockIdx.y * 128;
    const int bn = blockIdx.x * 128;
    const int wid = tid >> 5, lane = tid & 31;
    const int wm = (wid & 3) * 32;      // warp row offset (0..96)
    const int wn = (wid >> 2) * 64;     // warp col offset (0 / 64)
    const bool mguard = (Mrows & 127) != 0;

    // loader mapping: 2 threads per row, each 2x16B per half
    const int lrow = tid >> 1;
    const int lw = (tid & 1) * 2;
    const int am = bm + lrow;
    const bool av = !mguard || (am < Mrows);
    const size_t aoff = (size_t)(av ? am : 0) * K;
    const size_t boff = (size_t)(bn + lrow) * K;
    const uint32_t bline = (uint32_t)((lrow >> 1) * 128 + (lrow & 1) * 64);

    // A ldmatrix lane addressing (m16 x k16 per x4)
    const int a_mi = lane >> 3;
    const int a_row = (lane & 7) + (a_mi & 1) * 8;
    const int a_kb = (a_mi >> 1) * 16;
    // B ldmatrix lane addressing (2 n8 tiles x 2 k-halves per x4)
    const int b_g = lane >> 3;
    const int b_row = lane & 7;
    const int b_nt = b_g >> 1;
    const int b_kh = (b_g & 1) * 16;

    float c[16][4];                     // [mt*8 + nt][4], mt<2, nt<8
#pragma unroll
    for (int i = 0; i < 16; i++)
#pragma unroll
        for (int j = 0; j < 4; j++) c[i][j] = 0.f;

    const int NCH = K >> 5;

    auto load_stage = [&](int s, int k0) {
        const uint32_t sA = sbase + s * GSTAGE;
        const uint32_t sB = sA + ASTAGE;
#pragma unroll
        for (int it = 0; it < 2; it++) {
            const int word = lw + it;              // 0..3
            const uint32_t soh = SW128((uint32_t)(lrow * 128 + word * 16));
            const size_t ko = (size_t)(k0 + word * 8);
            cp16(sA + soh, Ah + aoff + ko, av);
            if (PASSES == 2) {
                const uint32_t sol = SW128((uint32_t)(lrow * 128 + 64 + word * 16));
                cp16(sA + sol, Al + aoff + ko, av);
            }
            cp16(sB + SW128(bline + word * 16), Bh + boff + ko, true);
        }
    };

    load_stage(0, 0);
    CP_COMMIT();
    load_stage(1, 32);
    CP_COMMIT();
    load_stage(2, 64);
    CP_COMMIT();

    int stage = 0;
    for (int ch = 0; ch < NCH; ch++) {
        cp_wait<2>();
        __syncthreads();
        if (ch + 3 < NCH) {
            int ns = stage + 3; if (ns >= NSTAGE) ns -= NSTAGE;
            load_stage(ns, (ch + 3) * 32);
        }
        CP_COMMIT();   // always commit (possibly empty) to keep accounting
        const uint32_t sAu = sbase + stage * GSTAGE;
        const uint32_t sBu = sAu + ASTAGE;
        // ---- compute: 2 k16 steps ----
#pragma unroll
        for (int k16 = 0; k16 < 2; k16++) {
            const int kb = k16 * 32;
            uint32_t bfrag[4][4];       // 8 n8 tiles (64 cols)
#pragma unroll
            for (int p = 0; p < 4; p++) {
                const int n = wn + (p * 2 + b_nt) * 8 + b_row;
                const uint32_t rb = (uint32_t)((n >> 1) * 128 + (n & 1) * 64);
                ldsm4(bfrag[p], sBu + SW128(rb + kb + b_kh));
            }
            uint32_t a[2][4];
#pragma unroll
            for (int mt = 0; mt < 2; mt++)
                ldsm4(a[mt], sAu + SW128((uint32_t)((wm + mt * 16 + a_row) * 128) + kb + a_kb));
#pragma unroll
            for (int mt = 0; mt < 2; mt++)
#pragma unroll
                for (int nt = 0; nt < 8; nt++)
                    mma16816(c[mt * 8 + nt], a[mt], &bfrag[nt >> 1][(nt & 1) * 2]);
            if (PASSES == 2) {
                // lo(A) pass
#pragma unroll
                for (int mt = 0; mt < 2; mt++)
                    ldsm4(a[mt], sAu + SW128((uint32_t)((wm + mt * 16 + a_row) * 128) + 64 + kb + a_kb));
#pragma unroll
                for (int mt = 0; mt < 2; mt++)
#pragma unroll
                    for (int nt = 0; nt < 8; nt++)
                        mma16816(c[mt * 8 + nt], a[mt], &bfrag[nt >> 1][(nt & 1) * 2]);
            }
        }
        if (++stage >= NSTAGE) stage = 0;
    }

    // ---- epilogue ----
    const int mrow = lane >> 2;
    const int mcol = (lane & 3) * 2;
#pragma unroll
    for (int mt = 0; mt < 2; mt++) {
        const int r0 = bm + wm + mt * 16 + mrow;
        const int r1 = r0 + 8;
        const bool v0 = !mguard || (r0 < Mrows);
        const bool v1 = !mguard || (r1 < Mrows);
        const float* e0 = nullptr;
        const float* e1 = nullptr;
        if (EPI == 1) {
            if (v0) e0 = embed + (size_t)seq[r0] * HID;
            if (v1) e1 = embed + (size_t)seq[r1] * HID;
        }
#pragma unroll
        for (int nt = 0; nt < 8; nt++) {
            const int col = bn + wn + nt * 8 + mcol;
            float* cc = c[mt * 8 + nt];
            const float b0v = bias[col], b1v = bias[col + 1];
            float x0 = cc[0] + b0v, x1 = cc[1] + b1v;
            float x2 = cc[2] + b0v, x3 = cc[3] + b1v;
            if (EPI == 0) {
                x0 = fmaxf(x0, 0.f); x1 = fmaxf(x1, 0.f);
                x2 = fmaxf(x2, 0.f); x3 = fmaxf(x3, 0.f);
                if (v0) {
                    __half2 ph; ph.x = __float2half_rn(x0); ph.y = __float2half_rn(x1);
                    *(__half2*)(Chi + (size_t)r0 * N + col) = ph;
                }
                if (v1) {
                    __half2 ph; ph.x = __float2half_rn(x2); ph.y = __float2half_rn(x3);
                    *(__half2*)(Chi + (size_t)r1 * N + col) = ph;
                }
            } else {
                if (EPI == 1) {
                    if (v0) { x0 += e0[col]; x1 += e0[col + 1]; }
                    if (v1) { x2 += e1[col]; x3 += e1[col + 1]; }
                }
                if (v0) *(float2*)(Cf + (size_t)r0 * N + col) = make_float2(x0, x1);
                if (v1) *(float2*)(Cf + (size_t)r1 * N + col) = make_float2(x2, x3);
            }
        }
    }
}

// ============================================================
// gather + round:  Ahi[m] = fp16(embed[seq[m]])
// ============================================================
__global__ void __launch_bounds__(256) gsplit_k(const int* __restrict__ seq,
                                                const float* __restrict__ embed,
                                                half_t* __restrict__ hi)
{
    const size_t idx = (size_t)blockIdx.x * 256 + threadIdx.x;   // TOK*64
    const int t = (int)(idx >> 6), c = (int)(idx & 63) * 8;
    const float* p = embed + (size_t)seq[t] * HID + c;
    float4 a = *(const float4*)p;
    float4 b = *(const float4*)(p + 4);
    float vv[8] = {a.x, a.y, a.z, a.w, b.x, b.y, b.z, b.w};
    const size_t ob = (size_t)t * HID + c;
#pragma unroll
    for (int j = 0; j < 8; j += 2) {
        __half2 ph; ph.x = __float2half_rn(vv[j]); ph.y = __float2half_rn(vv[j + 1]);
        *(__half2*)(hi + ob + j) = ph;
    }
}

// ============================================================
// Tiled transpose + round: W[K,N] fp32 -> out[N,K] single fp16.
// ============================================================
__global__ void __launch_bounds__(256) tsplit1_k(const float* __restrict__ W, int K, int N,
                                                 half_t* __restrict__ ht)
{
    __shared__ float t[32][33];
    const int tx = threadIdx.x & 31, ty = threadIdx.x >> 5;
    const int n0 = blockIdx.x * 32, k0 = blockIdx.y * 32;
#pragma unroll
    for (int i = 0; i < 4; i++)
        t[ty + 8 * i][tx] = W[(size_t)(k0 + ty + 8 * i) * N + n0 + tx];
    __syncthreads();
#pragma unroll
    for (int i = 0; i < 4; i++) {
        const size_t o = (size_t)(n0 + ty + 8 * i) * K + k0 + tx;
        ht[o] = __float2half_rn(t[tx][ty + 8 * i]);
    }
}

// ============================================================
// LayerNorm (warp per row) -> fp16 output.
// ============================================================
__global__ void __launch_bounds__(256) ln_split_k(const float* __restrict__ x,
                                                  const float* __restrict__ g,
                                                  const float* __restrict__ b,
                                                  half_t* __restrict__ hh)
{
    const int row = blockIdx.x * 8 + (threadIdx.x >> 5);
    const int ln = threadIdx.x & 31;
    const float* xr = x + (size_t)row * HID + ln * 16;
    float v[16];
    *(float4*)&v[0]  = ((const float4*)xr)[0];
    *(float4*)&v[4]  = ((const float4*)xr)[1];
    *(float4*)&v[8]  = ((const float4*)xr)[2];
    *(float4*)&v[12] = ((const float4*)xr)[3];
    float s = 0.f;
#pragma unroll
    for (int j = 0; j < 16; j++) s += v[j];
#pragma unroll
    for (int o = 16; o; o >>= 1) s += __shfl_xor_sync(0xffffffffu, s, o);
    const float mean = s * (1.f / 512.f);
    float q = 0.f;
#pragma unroll
    for (int j = 0; j < 16; j++) { float d = v[j] - mean; q += d * d; }
#pragma unroll
    for (int o = 16; o; o >>= 1) q += __shfl_xor_sync(0xffffffffu, q, o);
    const float r = rsqrtf(q * (1.f / 512.f) + 1e-5f);
    const size_t ob = (size_t)row * HID + ln * 16;
#pragma unroll
    for (int j = 0; j < 16; j += 2) {
        const int c0 = ln * 16 + j;
        float y0 = (v[j] - mean) * r * g[c0] + b[c0];
        float y1 = (v[j + 1] - mean) * r * g[c0 + 1] + b[c0 + 1];
        __half2 ph; ph.x = __float2half_rn(y0); ph.y = __float2half_rn(y1);
        *(__half2*)(hh + ob + j) = ph;
    }
}

// ============================================================
__global__ void bpack_k(const float* __restrict__ sb, const float* __restrict__ eb)
{
    const int i = blockIdx.x * 256 + threadIdx.x;
    if (i < HID) g_bproj[i] = (i < HALF_) ? sb[i] : eb[i - HALF_];
}

// ============================================================
// Backward vector scan, 2 steps per iteration, inline norms,
// depth-2 row prefetch, fp32 + split-fp16 outputs.
// ============================================================
__global__ void __launch_bounds__(32) scan_k(const float* __restrict__ kall,
                                             float* __restrict__ cbuf,
                                             half_t* __restrict__ chh,
                                             half_t* __restrict__ chl)
{
    const int chain = blockIdx.x;
    const int b = chain >> 1, wh = chain & 1;
    const int ln = threadIdx.x;
    const float* base = kall + (size_t)b * SEQL * HID + wh * HALF_ + ln * 8;

#define LOADROW(dst, t) do { \
    float4 _a = *(const float4*)(base + (size_t)(t) * HID); \
    float4 _b = *(const float4*)(base + (size_t)(t) * HID + 4); \
    dst[0]=_a.x; dst[1]=_a.y; dst[2]=_a.z; dst[3]=_a.w; \
    dst[4]=_b.x; dst[5]=_b.y; dst[6]=_b.z; dst[7]=_b.w; } while (0)

    float u[8], acc[8], k0[8], k1[8], p0[8], p1[8];
    LOADROW(u, SEQL - 1);
#pragma unroll
    for (int j = 0; j < 8; j++) acc[j] = 0.f;

    // ---- single first step t = 1022 ----
    {
        float kc[8];
        LOADROW(kc, SEQL - 2);
        LOADROW(k0, SEQL - 3);   // t=1021
        LOADROW(k1, SEQL - 4);   // t=1020
        LOADROW(p0, SEQL - 5);   // t=1019
        LOADROW(p1, SEQL - 6);   // t=1018
        float pa = 0.f, n0 = 0.f;
#pragma unroll
        for (int j = 0; j < 8; j++) { pa += kc[j] * u[j]; n0 += kc[j] * kc[j]; }
#pragma unroll
        for (int o = 16; o; o >>= 1) {
            pa += __shfl_xor_sync(0xffffffffu, pa, o);
            n0 += __shfl_xor_sync(0xffffffffu, n0, o);
        }
        const float w = wh ? (1023.f / 1024.f) : 1.f;
        const float ws = w * pa;
        const float us = ws / (n0 + 1e-6f);
#pragma unroll
        for (int j = 0; j < 8; j++) { acc[j] += ws * kc[j]; u[j] -= us * kc[j]; }
    }

    // ---- pair loop: t = 1021, 1019, ..., 1 (511 iterations) ----
    for (int t = SEQL - 3; t >= 1; t -= 2) {
        float q0[8] = {0, 0, 0, 0, 0, 0, 0, 0};
        float q1[8] = {0, 0, 0, 0, 0, 0, 0, 0};
        if (t >= 5) {
            LOADROW(q0, t - 4);
            LOADROW(q1, t - 5);
        }
        float pa = 0.f, pb = 0.f, pg = 0.f, n0 = 0.f, n1 = 0.f;
#pragma unroll
        for (int j = 0; j < 8; j++) {
            pa += k0[j] * u[j];
            pb += k1[j] * u[j];
            pg += k1[j] * k0[j];
            n0 += k0[j] * k0[j];
            n1 += k1[j] * k1[j];
        }
#pragma unroll
        for (int o = 16; o; o >>= 1) {
            pa += __shfl_xor_sync(0xffffffffu, pa, o);
            pb += __shfl_xor_sync(0xffffffffu, pb, o);
            pg += __shfl_xor_sync(0xffffffffu, pg, o);
            n0 += __shfl_xor_sync(0xffffffffu, n0, o);
            n1 += __shfl_xor_sync(0xffffffffu, n1, o);
        }
        const float inv1024 = 1.f / 1024.f;
        const float w0 = wh ? (float)(t + 1) * inv1024 : 1.f;
        const float w1 = wh ? (float)t * inv1024 : 1.f;
        const float id0 = 1.f / (n0 + 1e-6f);
        const float id1 = 1.f / (n1 + 1e-6f);
        const float ws0 = w0 * pa;
        const float us0 = ws0 * id0;
        const float s1 = pb - us0 * pg;
        const float ws1 = w1 * s1;
        const float us1 = ws1 * id1;
#pragma unroll
        for (int j = 0; j < 8; j++) {
            acc[j] += ws0 * k0[j] + ws1 * k1[j];
            u[j]   -= us0 * k0[j] + us1 * k1[j];
        }
#pragma unroll
        for (int j = 0; j < 8; j++) {
            k0[j] = p0[j]; k1[j] = p1[j];
            p0[j] = q0[j]; p1[j] = q1[j];
        }
    }

    const size_t ob = (size_t)b * HID + wh * HALF_ + ln * 8;
    *(float4*)(cbuf + ob)     = make_float4(acc[0], acc[1], acc[2], acc[3]);
    *(float4*)(cbuf + ob + 4) = make_float4(acc[4], acc[5], acc[6], acc[7]);
#pragma unroll
    for (int j = 0; j < 8; j += 2) {
        half_t h0, l0, h1, l1;
        split2h(acc[j], h0, l0);
        split2h(acc[j + 1], h1, l1);
        __half2 ph; ph.x = h0; ph.y = h1;
        __half2 pl; pl.x = l0; pl.y = l1;
        *(__half2*)(chh + ob + j) = ph;
        *(__half2*)(chl + ob + j) = pl;
    }
#undef LOADROW
}

// ============================================================
extern "C" void kernel_launch(void* const* d_in, const int* in_sizes, int n_in,
                              void* d_out, int out_size)
{
    const int*   seq   = (const int*)d_in[0];
    const float* embed = (const float*)d_in[1];
    const float* w1    = (const float*)d_in[2];
    const float* b1    = (const float*)d_in[3];
    const float* w2    = (const float*)d_in[4];
    const float* b2    = (const float*)d_in[5];
    const float* lng   = (const float*)d_in[6];
    const float* lnb   = (const float*)d_in[7];
    const float* sw    = (const float*)d_in[8];
    const float* sb    = (const float*)d_in[9];
    const float* ew    = (const float*)d_in[10];
    const float* eb    = (const float*)d_in[11];
    const float* ow    = (const float*)d_in[12];
    const float* ob    = (const float*)d_in[13];
    float* out = (float*)d_out;

    static bool init = false;
    static half_t *ah, *h1h, *hh, *w1h, *w2h, *wph, *owh, *ch, *cl;
    static float *xb, *kb, *bp, *cb;
    if (!init) {
        cudaGetSymbolAddress((void**)&ah,  g_ah);
        cudaGetSymbolAddress((void**)&h1h, g_h1h);
        cudaGetSymbolAddress((void**)&hh,  g_hh);
        cudaGetSymbolAddress((void**)&w1h, g_w1h);
        cudaGetSymbolAddress((void**)&w2h, g_w2h);
        cudaGetSymbolAddress((void**)&wph, g_wph);
        cudaGetSymbolAddress((void**)&owh, g_owh);
        cudaGetSymbolAddress((void**)&ch,  g_ch);   cudaGetSymbolAddress((void**)&cl,  g_cl);
        cudaGetSymbolAddress((void**)&xb,  g_x);
        cudaGetSymbolAddress((void**)&kb,  g_k);
        cudaGetSymbolAddress((void**)&bp,  g_bproj);
        cudaGetSymbolAddress((void**)&cb,  g_c);
        cudaFuncSetAttribute(mma_gemm<0, 1>, cudaFuncAttributeMaxDynamicSharedMemorySize, GSMEM);
        cudaFuncSetAttribute(mma_gemm<1, 1>, cudaFuncAttributeMaxDynamicSharedMemorySize, GSMEM);
        cudaFuncSetAttribute(mma_gemm<2, 1>, cudaFuncAttributeMaxDynamicSharedMemorySize, GSMEM);
        cudaFuncSetAttribute(mma_gemm<2, 2>, cudaFuncAttributeMaxDynamicSharedMemorySize, GSMEM);
        init = true;
    }

    // weight transpose + fp16 round (B operands are [N,K] K-major, single fp16)
    tsplit1_k<<<dim3(FF / 32, HID / 32), 256>>>(w1, HID, FF, w1h);
    tsplit1_k<<<dim3(HID / 32, FF / 32), 256>>>(w2, FF, HID, w2h);
    tsplit1_k<<<dim3(HALF_ / 32, HID / 32), 256>>>(sw, HID, HALF_, wph);
    tsplit1_k<<<dim3(HALF_ / 32, HID / 32), 256>>>(ew, HID, HALF_, wph + (size_t)HALF_ * HID);
    tsplit1_k<<<dim3(VOC / 32, HID / 32), 256>>>(ow, HID, VOC, owh);
    bpack_k<<<2, 256>>>(sb, eb);

    // A operand for GEMM1: gathered embeddings (fp16)
    gsplit_k<<<TOK * 64 / 256, 256>>>(seq, embed, ah);

    // GEMM1: relu(e @ w1 + b1) -> h1 (fp16)         [65536 x 1024, K=512]
    mma_gemm<0, 1><<<dim3(FF / 128, TOK / 128), 256, GSMEM>>>(
        TOK, FF, HID, ah, nullptr, w1h, b1, nullptr, h1h, nullptr, nullptr);

    // GEMM2: x = h1 @ w2 + b2 + e  -> fp32          [65536 x 512, K=1024]
    mma_gemm<1, 1><<<dim3(HID / 128, TOK / 128), 256, GSMEM>>>(
        TOK, HID, FF, h1h, nullptr, w2h, b2, xb, nullptr, seq, embed);

    // LayerNorm -> h (fp16)
    ln_split_k<<<TOK / 8, 256>>>(xb, lng, lnb, hh);

    // GEMM3: k = h @ [sem|epi] + bias -> fp32       [65536 x 512, K=512]
    mma_gemm<2, 1><<<dim3(HID / 128, TOK / 128), 256, GSMEM>>>(
        TOK, HID, HID, hh, nullptr, wph, bp, kb, nullptr, nullptr, nullptr);

    // backward scan (norms fused, fp16 split fused) -> c
    scan_k<<<128, 32>>>(kb, cb, ch, cl);

    // GEMM4: out = c @ out_w + out_b  (2-pass A)    [64 x 32000, K=512]
    mma_gemm<2, 2><<<dim3(VOC / 128, 1), 256, GSMEM>>>(
        BATCH, VOC, HID, ch, cl, owh, ob, out, nullptr, nullptr, nullptr);
}